// round 5
// baseline (speedup 1.0000x reference)
#include <cuda_runtime.h>
#include <math.h>
#include <stdint.h>

// ---------------------------------------------------------------------------
// Problem constants
// ---------------------------------------------------------------------------
#define B_   2
#define T_   2048
#define D_   1024
#define H_   16
#define NKV  64
#define NF_  4096
#define MBT  (B_ * T_)        // 4096 rows (b,t) flattened

// ---------------------------------------------------------------------------
// Scratch buffers (device globals; allocation is forbidden).
// ---------------------------------------------------------------------------
__device__ float g_q[(size_t)B_ * H_ * T_ * NKV];     // [B,H,T,64]
__device__ float g_k[(size_t)B_ * H_ * T_ * NKV];
__device__ float g_v[(size_t)B_ * H_ * T_ * NKV];
__device__ float g_ocat[(size_t)MBT * D_];            // [B,T,H*64] concat heads
__device__ float g_attn[(size_t)MBT * D_];            // o-proj output
__device__ float g_h[(size_t)MBT * D_];               // after LN1
__device__ float g_f[(size_t)MBT * NF_];              // relu(h@W1+b1)
__device__ float g_y[(size_t)MBT * D_];               // ffn output

#define ID_Q    0
#define ID_K    1
#define ID_V    2
#define ID_OCAT 3
#define ID_ATTN 4
#define ID_H    5
#define ID_F    6
#define ID_Y    7

__device__ __forceinline__ float* gbuf(int id) {
    switch (id) {
        case ID_Q:    return g_q;
        case ID_K:    return g_k;
        case ID_V:    return g_v;
        case ID_OCAT: return g_ocat;
        case ID_ATTN: return g_attn;
        case ID_H:    return g_h;
        case ID_F:    return g_f;
        default:      return g_y;
    }
}

// ---------------------------------------------------------------------------
// tf32 helpers (3xTF32 split: v = hi + lo, both tf32-representable)
// ---------------------------------------------------------------------------
__device__ __forceinline__ void split_tf32(float v, uint32_t& hi, uint32_t& lo) {
    uint32_t uh = __float_as_uint(v) & 0xffffe000u;
    hi = uh;
    lo = __float_as_uint(v - __uint_as_float(uh)) & 0xffffe000u;
}

__device__ __forceinline__ void mma_tf32(float* c, const uint32_t* a,
                                         uint32_t b0, uint32_t b1) {
    asm volatile(
        "mma.sync.aligned.m16n8k8.row.col.f32.tf32.tf32.f32 "
        "{%0,%1,%2,%3}, {%4,%5,%6,%7}, {%8,%9}, {%0,%1,%2,%3};\n"
        : "+f"(c[0]), "+f"(c[1]), "+f"(c[2]), "+f"(c[3])
        : "r"(a[0]), "r"(a[1]), "r"(a[2]), "r"(a[3]), "r"(b0), "r"(b1));
}

// ---------------------------------------------------------------------------
// Tensor-core GEMM (3xTF32): C[M,N] = A[M,K] @ B[K,N] (+bias) (+relu)
// BM=128, BN=128, BK=16, 256 threads (8 warps, 4x2), warp tile 32x64.
// bmode: 0 = B row-major [K,N];  1 = B packed per-head [H, K, 64] (QKV weights)
// cmode: 0 = C row-major [M,N];  1 = C scattered to [B,H,T,64] (QKV outputs)
// ---------------------------------------------------------------------------
__global__ __launch_bounds__(256)
void gemm_tc(const float* __restrict__ Aext, int aId,
             const float* __restrict__ Bm, const float* __restrict__ bias,
             int cId, int N, int K, int bmode, int cmode, int relu)
{
    __shared__ float As[128][20];   // [m][k], k stride 20 -> conflict-free frags
    __shared__ float Bs[128][20];   // [n][k]

    const float* Ab = (aId >= 0) ? gbuf(aId) : Aext;
    float*       Cb = gbuf(cId);

    const int tid  = threadIdx.x;
    const int brow = blockIdx.y * 128;
    const int bcol = blockIdx.x * 128;

    // global->smem assignments
    const int am = tid >> 1;                 // 0..127
    const int akq = (tid & 1) * 8;           // 0 or 8
    const float* Aptr = Ab + (size_t)(brow + am) * K + akq;

    const int kb = tid & 15;                 // B k-row 0..15
    const int ng = tid >> 4;                 // 0..15
    const int n0 = ng * 8;                   // 8 cols per thread

    // warp/frag coords
    const int warp = tid >> 5;
    const int lane = tid & 31;
    const int wm = warp >> 1;                // 0..3 -> row base wm*32
    const int wn = warp & 1;                 // 0..1 -> col base wn*64
    const int grp = lane >> 2;               // 0..7
    const int tig = lane & 3;                // 0..3

    float acc[2][8][4];
#pragma unroll
    for (int mt = 0; mt < 2; mt++)
#pragma unroll
        for (int nt = 0; nt < 8; nt++)
#pragma unroll
            for (int i = 0; i < 4; i++) acc[mt][nt][i] = 0.f;

    for (int kk = 0; kk < K; kk += 16) {
        // global loads
        float4 av0 = *(const float4*)(Aptr + kk);
        float4 av1 = *(const float4*)(Aptr + kk + 4);
        float4 bv0, bv1;
        if (bmode == 0) {
            const float* bp = Bm + (size_t)(kk + kb) * N + bcol + n0;
            bv0 = *(const float4*)(bp);
            bv1 = *(const float4*)(bp + 4);
        } else {
            const int d  = kk + kb;
            const int j0 = bcol + n0;
            const float* bp = Bm + (size_t)(j0 >> 6) * K * 64 +
                              (size_t)d * 64 + (j0 & 63);
            bv0 = *(const float4*)(bp);
            bv1 = *(const float4*)(bp + 4);
        }

        __syncthreads();
        // A stores
        As[am][akq + 0] = av0.x; As[am][akq + 1] = av0.y;
        As[am][akq + 2] = av0.z; As[am][akq + 3] = av0.w;
        As[am][akq + 4] = av1.x; As[am][akq + 5] = av1.y;
        As[am][akq + 6] = av1.z; As[am][akq + 7] = av1.w;
        // B stores (transpose to [n][k])
        Bs[n0 + 0][kb] = bv0.x; Bs[n0 + 1][kb] = bv0.y;
        Bs[n0 + 2][kb] = bv0.z; Bs[n0 + 3][kb] = bv0.w;
        Bs[n0 + 4][kb] = bv1.x; Bs[n0 + 5][kb] = bv1.y;
        Bs[n0 + 6][kb] = bv1.z; Bs[n0 + 7][kb] = bv1.w;
        __syncthreads();

#pragma unroll
        for (int k0 = 0; k0 < 16; k0 += 8) {
            // A fragments (hi/lo)
            uint32_t ah[2][4], alo[2][4];
#pragma unroll
            for (int mt = 0; mt < 2; mt++) {
                const int r0 = wm * 32 + mt * 16 + grp;
                split_tf32(As[r0    ][k0 + tig],     ah[mt][0], alo[mt][0]);
                split_tf32(As[r0 + 8][k0 + tig],     ah[mt][1], alo[mt][1]);
                split_tf32(As[r0    ][k0 + 4 + tig], ah[mt][2], alo[mt][2]);
                split_tf32(As[r0 + 8][k0 + 4 + tig], ah[mt][3], alo[mt][3]);
            }
#pragma unroll
            for (int nt = 0; nt < 8; nt++) {
                const int n = wn * 64 + nt * 8 + grp;
                uint32_t bh0, bl0, bh1, bl1;
                split_tf32(Bs[n][k0 + tig],     bh0, bl0);
                split_tf32(Bs[n][k0 + 4 + tig], bh1, bl1);
#pragma unroll
                for (int mt = 0; mt < 2; mt++) {
                    mma_tf32(acc[mt][nt], ah[mt],  bh0, bh1);
                    mma_tf32(acc[mt][nt], ah[mt],  bl0, bl1);
                    mma_tf32(acc[mt][nt], alo[mt], bh0, bh1);
                }
            }
        }
    }

    // epilogue
#pragma unroll
    for (int mt = 0; mt < 2; mt++) {
#pragma unroll
        for (int nt = 0; nt < 8; nt++) {
            const int row = brow + wm * 32 + mt * 16 + grp;
            const int col = bcol + wn * 64 + nt * 8 + 2 * tig;
            float b0 = bias ? bias[col]     : 0.f;
            float b1 = bias ? bias[col + 1] : 0.f;
            float v00 = acc[mt][nt][0] + b0, v01 = acc[mt][nt][1] + b1;
            float v10 = acc[mt][nt][2] + b0, v11 = acc[mt][nt][3] + b1;
            if (relu) {
                v00 = fmaxf(v00, 0.f); v01 = fmaxf(v01, 0.f);
                v10 = fmaxf(v10, 0.f); v11 = fmaxf(v11, 0.f);
            }
            if (cmode == 0) {
                *(float2*)(Cb + (size_t)row * N + col)       = make_float2(v00, v01);
                *(float2*)(Cb + (size_t)(row + 8) * N + col) = make_float2(v10, v11);
            } else {
                const int h  = col >> 6, cc = col & 63;
                const int b  = row >> 11;          // T_ = 2048
                const int t  = row & 2047;
                float* p0 = Cb + ((size_t)(b * H_ + h) * T_ + t) * 64 + cc;
                *(float2*)p0            = make_float2(v00, v01);
                *(float2*)(p0 + 8 * 64) = make_float2(v10, v11);  // row+8 -> t+8
            }
        }
    }
}

// ---------------------------------------------------------------------------
// Causal flash attention (fp32, online softmax; 4 threads per softmax row).
// Block = (q-tile of 64 rows) x (head) x (batch); 256 threads; d=64.
// ---------------------------------------------------------------------------
#define APAD 65
__global__ __launch_bounds__(256)
void attn_kernel() {
    extern __shared__ float sm[];
    float* Qs   = sm;
    float* Ks   = Qs + 64 * APAD;
    float* Vs   = Ks + 64 * APAD;
    float* Ss   = Vs + 64 * APAD;
    float* mrow = Ss + 64 * APAD;   // 64
    float* lrow = mrow + 64;        // 64
    float* arow = lrow + 64;        // 64

    const int qi = blockIdx.x;
    const int h  = blockIdx.y;
    const int b  = blockIdx.z;
    const int tid = threadIdx.x;
    const int tr4 = (tid >> 4) * 4;
    const int tc4 = (tid & 15) * 4;
    const float scale = 0.125f;     // 1/sqrt(64)
    const float NEG = -1e30f;

    const size_t base = (size_t)(b * H_ + h) * T_ * NKV;

    for (int i = tid; i < 64 * 16; i += 256) {
        const int r = i >> 4, c4 = (i & 15) << 2;
        float4 qv = *(const float4*)(g_q + base + (size_t)(qi * 64 + r) * NKV + c4);
        Qs[r * APAD + c4 + 0] = qv.x; Qs[r * APAD + c4 + 1] = qv.y;
        Qs[r * APAD + c4 + 2] = qv.z; Qs[r * APAD + c4 + 3] = qv.w;
    }
    if (tid < 64) { mrow[tid] = NEG; lrow[tid] = 0.f; }

    float acc[4][4];
#pragma unroll
    for (int i = 0; i < 4; i++)
#pragma unroll
        for (int j = 0; j < 4; j++) acc[i][j] = 0.f;

    for (int jt = 0; jt <= qi; jt++) {
        __syncthreads();
        for (int i = tid; i < 64 * 16; i += 256) {
            const int r = i >> 4, c4 = (i & 15) << 2;
            const size_t off = base + (size_t)(jt * 64 + r) * NKV + c4;
            float4 kv = *(const float4*)(g_k + off);
            float4 vv = *(const float4*)(g_v + off);
            Ks[r * APAD + c4 + 0] = kv.x; Ks[r * APAD + c4 + 1] = kv.y;
            Ks[r * APAD + c4 + 2] = kv.z; Ks[r * APAD + c4 + 3] = kv.w;
            Vs[r * APAD + c4 + 0] = vv.x; Vs[r * APAD + c4 + 1] = vv.y;
            Vs[r * APAD + c4 + 2] = vv.z; Vs[r * APAD + c4 + 3] = vv.w;
        }
        __syncthreads();

        // S = Q K^T * scale (each thread 4x4)
        float s[4][4];
#pragma unroll
        for (int i = 0; i < 4; i++)
#pragma unroll
            for (int j = 0; j < 4; j++) s[i][j] = 0.f;
#pragma unroll 8
        for (int d = 0; d < 64; d++) {
            float rq[4], rk[4];
#pragma unroll
            for (int i = 0; i < 4; i++) rq[i] = Qs[(tr4 + i) * APAD + d];
#pragma unroll
            for (int j = 0; j < 4; j++) rk[j] = Ks[(tc4 + j) * APAD + d];
#pragma unroll
            for (int i = 0; i < 4; i++)
#pragma unroll
                for (int j = 0; j < 4; j++) s[i][j] += rq[i] * rk[j];
        }
        const bool diag = (jt == qi);
#pragma unroll
        for (int i = 0; i < 4; i++) {
            const int rr = tr4 + i;
#pragma unroll
            for (int j = 0; j < 4; j++) {
                const int cc = tc4 + j;
                float val = s[i][j] * scale;
                if (diag && cc > rr) val = NEG;
                Ss[rr * APAD + cc] = val;
            }
        }
        __syncthreads();

        // online softmax: 4 threads per row (quad of consecutive lanes)
        {
            const int r  = tid >> 2;
            const int cq = (tid & 3) * 16;
            float mx = NEG;
#pragma unroll
            for (int c = 0; c < 16; c++) mx = fmaxf(mx, Ss[r * APAD + cq + c]);
            mx = fmaxf(mx, __shfl_xor_sync(0xffffffffu, mx, 1));
            mx = fmaxf(mx, __shfl_xor_sync(0xffffffffu, mx, 2));
            const float mo = mrow[r];
            mx = fmaxf(mx, mo);
            float sum = 0.f;
#pragma unroll
            for (int c = 0; c < 16; c++) {
                float p = __expf(Ss[r * APAD + cq + c] - mx);
                Ss[r * APAD + cq + c] = p;
                sum += p;
            }
            sum += __shfl_xor_sync(0xffffffffu, sum, 1);
            sum += __shfl_xor_sync(0xffffffffu, sum, 2);
            if ((tid & 3) == 0) {
                const float al = __expf(mo - mx);
                lrow[r] = lrow[r] * al + sum;
                mrow[r] = mx;
                arow[r] = al;
            }
        }
        __syncthreads();

        // rescale accumulators, then O += P @ V
#pragma unroll
        for (int i = 0; i < 4; i++) {
            const float al = arow[tr4 + i];
#pragma unroll
            for (int j = 0; j < 4; j++) acc[i][j] *= al;
        }
#pragma unroll 8
        for (int c = 0; c < 64; c++) {
            float rp[4], rv[4];
#pragma unroll
            for (int i = 0; i < 4; i++) rp[i] = Ss[(tr4 + i) * APAD + c];
#pragma unroll
            for (int j = 0; j < 4; j++) rv[j] = Vs[c * APAD + tc4 + j];
#pragma unroll
            for (int i = 0; i < 4; i++)
#pragma unroll
                for (int j = 0; j < 4; j++) acc[i][j] += rp[i] * rv[j];
        }
    }

#pragma unroll
    for (int i = 0; i < 4; i++) {
        const int rr = tr4 + i;
        const float inv = 1.f / lrow[rr];
        const size_t rowoff = ((size_t)b * T_ + (size_t)qi * 64 + rr) * D_ + h * NKV;
#pragma unroll
        for (int j = 0; j < 4; j++)
            g_ocat[rowoff + tc4 + j] = acc[i][j] * inv;
    }
}

// ---------------------------------------------------------------------------
// LayerNorm (unchanged from round 1)
// ---------------------------------------------------------------------------
__device__ __forceinline__ float block_sum(float v, float* red) {
    __syncthreads();
#pragma unroll
    for (int o = 16; o > 0; o >>= 1) v += __shfl_down_sync(0xffffffffu, v, o);
    if ((threadIdx.x & 31) == 0) red[threadIdx.x >> 5] = v;
    __syncthreads();
    if (threadIdx.x < 32) {
        float w = (threadIdx.x < 8) ? red[threadIdx.x] : 0.f;
#pragma unroll
        for (int o = 4; o > 0; o >>= 1) w += __shfl_down_sync(0xffffffffu, w, o);
        if (threadIdx.x == 0) red[0] = w;
    }
    __syncthreads();
    return red[0];
}

__global__ __launch_bounds__(256)
void ln_kernel(int aId, const float* __restrict__ res,
               const float* __restrict__ cbias, const float* __restrict__ g,
               const float* __restrict__ beta,
               float* __restrict__ out_ext, int outId, int addPre) {
    __shared__ float pre[D_];
    __shared__ float red[32];
    const int row = blockIdx.x;
    const int tid = threadIdx.x;
    const float* ap = gbuf(aId) + (size_t)row * D_;
    const float* rp = res ? res + (size_t)row * D_ : nullptr;
    float* out = (outId >= 0) ? gbuf(outId) : out_ext;

    float ls = 0.f;
    for (int i = tid; i < D_; i += 256) {
        float v = ap[i];
        if (rp)    v += rp[i];
        if (cbias) v += cbias[i];
        pre[i] = v;
        ls += v;
    }
    const float mean = block_sum(ls, red) * (1.f / D_);
    float lv = 0.f;
    for (int i = tid; i < D_; i += 256) {
        const float d = pre[i] - mean;
        lv += d * d;
    }
    const float var = block_sum(lv, red) * (1.f / D_);
    const float rstd = rsqrtf(var + 1e-5f);
    for (int i = tid; i < D_; i += 256) {
        const float p = pre[i];
        const float z = (p - mean) * rstd * g[i] + beta[i];
        out[(size_t)row * D_ + i] = z + (addPre ? p : 0.f);
    }
}

// ---------------------------------------------------------------------------
// Launcher
// ---------------------------------------------------------------------------
extern "C" void kernel_launch(void* const* d_in, const int* in_sizes, int n_in,
                              void* d_out, int out_size) {
    const float* x    = (const float*)d_in[0];
    const float* Wq   = (const float*)d_in[1];
    const float* bq   = (const float*)d_in[2];
    const float* Wk   = (const float*)d_in[3];
    const float* bk   = (const float*)d_in[4];
    const float* Wv   = (const float*)d_in[5];
    const float* bv   = (const float*)d_in[6];
    const float* Wo   = (const float*)d_in[7];
    const float* bo   = (const float*)d_in[8];
    const float* ln1g = (const float*)d_in[9];
    const float* ln1b = (const float*)d_in[10];
    const float* W1   = (const float*)d_in[11];
    const float* b1   = (const float*)d_in[12];
    const float* W2   = (const float*)d_in[13];
    const float* b2   = (const float*)d_in[14];
    const float* ln2g = (const float*)d_in[15];
    const float* ln2b = (const float*)d_in[16];
    float* out = (float*)d_out;

    // 1) QKV projections: one combined 4096x1024x1024 TC GEMM each
    dim3 gNarrow(D_ / 128, MBT / 128);          // (8, 32)
    gemm_tc<<<gNarrow, 256>>>(x, -1, Wq, bq, ID_Q, D_, D_, 1, 1, 0);
    gemm_tc<<<gNarrow, 256>>>(x, -1, Wk, bk, ID_K, D_, D_, 1, 1, 0);
    gemm_tc<<<gNarrow, 256>>>(x, -1, Wv, bv, ID_V, D_, D_, 1, 1, 0);

    // 2) Flash attention (causal)
    const int smem = (4 * 64 * APAD + 3 * 64) * (int)sizeof(float);  // 67328
    cudaFuncSetAttribute(attn_kernel,
                         cudaFuncAttributeMaxDynamicSharedMemorySize, smem);
    attn_kernel<<<dim3(T_ / 64, H_, B_), 256, smem>>>();

    // 3) Output projection (bo folded into LN1)
    gemm_tc<<<gNarrow, 256>>>(nullptr, ID_OCAT, Wo, nullptr, ID_ATTN, D_, D_, 0, 0, 0);

    // 4) h = LN(x + attn_out + bo)
    ln_kernel<<<MBT, 256>>>(ID_ATTN, x, bo, ln1g, ln1b, nullptr, ID_H, 0);

    // 5) FFN
    gemm_tc<<<dim3(NF_ / 128, MBT / 128), 256>>>(nullptr, ID_H, W1, b1, ID_F, NF_, D_, 0, 0, 1);
    gemm_tc<<<gNarrow, 256>>>(nullptr, ID_F, W2, b2, ID_Y, D_, NF_, 0, 0, 0);

    // 6) out = LN(y) + y
    ln_kernel<<<MBT, 256>>>(ID_Y, nullptr, nullptr, ln2g, ln2b, out, -1, 1);
}

// round 6
// speedup vs baseline: 1.9417x; 1.9417x over previous
#include <cuda_runtime.h>
#include <cuda_bf16.h>
#include <math.h>
#include <stdint.h>

#define B_   2
#define T_   2048
#define D_   1024
#define H_   16
#define NF_  4096
#define MBT  (B_ * T_)
#define NPL ((size_t)B_ * H_ * T_ * 64)

// bf16 hi/lo planes for q/k/v, written by QKV GEMM epilogue
__device__ __align__(16) unsigned short g_qh[NPL], g_ql[NPL];
__device__ __align__(16) unsigned short g_kh[NPL], g_kl[NPL];
__device__ __align__(16) unsigned short g_vh[NPL], g_vl[NPL];
__device__ float g_ocat[(size_t)MBT * D_];
__device__ float g_attn[(size_t)MBT * D_];
__device__ float g_h[(size_t)MBT * D_];
__device__ float g_f[(size_t)MBT * NF_];
__device__ float g_y[(size_t)MBT * D_];

#define ID_OCAT 0
#define ID_ATTN 1
#define ID_H    2
#define ID_F    3
#define ID_Y    4
__device__ __forceinline__ float* gbuf(int id) {
    switch (id) {
        case ID_OCAT: return g_ocat;
        case ID_ATTN: return g_attn;
        case ID_H:    return g_h;
        case ID_F:    return g_f;
        default:      return g_y;
    }
}

// ---------------- helpers ----------------
__device__ __forceinline__ void splitpack(float x, float y,
                                          unsigned& hi, unsigned& lo) {
    __nv_bfloat16 xh = __float2bfloat16(x);
    __nv_bfloat16 yh = __float2bfloat16(y);
    __nv_bfloat16 xl = __float2bfloat16(x - __bfloat162float(xh));
    __nv_bfloat16 yl = __float2bfloat16(y - __bfloat162float(yh));
    hi = (unsigned)__bfloat16_as_ushort(xh) | ((unsigned)__bfloat16_as_ushort(yh) << 16);
    lo = (unsigned)__bfloat16_as_ushort(xl) | ((unsigned)__bfloat16_as_ushort(yl) << 16);
}
__device__ __forceinline__ unsigned cvsm(const void* p) {
    return (unsigned)__cvta_generic_to_shared(p);
}
__device__ __forceinline__ void ldsm4(unsigned* r, unsigned a) {
    asm volatile("ldmatrix.sync.aligned.m8n8.x4.shared.b16 {%0,%1,%2,%3}, [%4];"
                 : "=r"(r[0]), "=r"(r[1]), "=r"(r[2]), "=r"(r[3]) : "r"(a));
}
__device__ __forceinline__ void ldsm2(unsigned& r0, unsigned& r1, unsigned a) {
    asm volatile("ldmatrix.sync.aligned.m8n8.x2.shared.b16 {%0,%1}, [%2];"
                 : "=r"(r0), "=r"(r1) : "r"(a));
}
__device__ __forceinline__ void ldsm2t(unsigned& r0, unsigned& r1, unsigned a) {
    asm volatile("ldmatrix.sync.aligned.m8n8.x2.trans.shared.b16 {%0,%1}, [%2];"
                 : "=r"(r0), "=r"(r1) : "r"(a));
}
__device__ __forceinline__ void mma_bf(float* c, const unsigned* a,
                                       unsigned b0, unsigned b1) {
    asm volatile(
        "mma.sync.aligned.m16n8k16.row.col.f32.bf16.bf16.f32 "
        "{%0,%1,%2,%3}, {%4,%5,%6,%7}, {%8,%9}, {%0,%1,%2,%3};\n"
        : "+f"(c[0]), "+f"(c[1]), "+f"(c[2]), "+f"(c[3])
        : "r"(a[0]), "r"(a[1]), "r"(a[2]), "r"(a[3]), "r"(b0), "r"(b1));
}
// fast e^x for x<=0, FMA pipe only, rel err ~2.4e-6
__device__ __forceinline__ float fexpf(float x) {
    x = fmaxf(x, -87.0f);
    float t = fmaf(x, 1.4426950408889634f, 12582912.0f);
    int   ni = __float_as_int(t) - 0x4B400000;
    float n  = t - 12582912.0f;
    float f  = fmaf(x, 1.4426950408889634f, -n);
    float p = 1.333355626e-3f;
    p = fmaf(p, f, 9.618129633e-3f);
    p = fmaf(p, f, 5.550410866e-2f);
    p = fmaf(p, f, 2.402265069e-1f);
    p = fmaf(p, f, 6.931471806e-1f);
    p = fmaf(p, f, 1.0f);
    return p * __int_as_float((ni + 127) << 23);
}

// ---------------------------------------------------------------------------
// GEMM bf16-split 3-term: C = A[M,K] @ B[K,N] (+bias)(+relu)
// BM=128 BN=128 BK=32, 256 thr, 8 warps (4x2), warp tile 32x64.
// bmode: 0 B row-major [K,N]; 1 B per-head [H,K,64]
// cmode: 0 C fp32 row-major (gbuf cId); 1 C -> bf16 planes (cId 0/1/2 = q/k/v)
// ---------------------------------------------------------------------------
__global__ __launch_bounds__(256)
void gemm_bf3(const float* __restrict__ Aext, int aId,
              const float* __restrict__ Bm, const float* __restrict__ bias,
              int cId, int N, int K, int bmode, int cmode, int relu)
{
    __shared__ __align__(16) unsigned short AsH[128 * 40];
    __shared__ __align__(16) unsigned short AsL[128 * 40];
    __shared__ __align__(16) unsigned short BsH[32 * 136];
    __shared__ __align__(16) unsigned short BsL[32 * 136];

    const float* Ab = (aId >= 0) ? gbuf(aId) : Aext;
    const int tid = threadIdx.x;
    const int brow = blockIdx.y * 128, bcol = blockIdx.x * 128;
    const int warp = tid >> 5, lane = tid & 31;
    const int wm = warp >> 1, wn = warp & 1;
    const int grp = lane >> 2, tig = lane & 3;
    const int lr = lane & 7, ls = lane >> 3, lb = lane & 15;
    const int arow = tid >> 1, akq = (tid & 1) * 16;
    const int bkr = tid >> 3, bn0 = (tid & 7) * 16;
    const unsigned aH = cvsm(AsH), aL = cvsm(AsL);
    const unsigned bH = cvsm(BsH), bL = cvsm(BsL);

    float acc[2][8][4];
#pragma unroll
    for (int mt = 0; mt < 2; mt++)
#pragma unroll
        for (int nt = 0; nt < 8; nt++)
#pragma unroll
            for (int i = 0; i < 4; i++) acc[mt][nt][i] = 0.f;

    float4 ra[4], rb[4];
    {
        const float* ap = Ab + (size_t)(brow + arow) * K + akq;
#pragma unroll
        for (int j = 0; j < 4; j++) ra[j] = *(const float4*)(ap + 4 * j);
        if (bmode == 0) {
            const float* bp = Bm + (size_t)bkr * N + bcol + bn0;
#pragma unroll
            for (int j = 0; j < 4; j++) rb[j] = *(const float4*)(bp + 4 * j);
        } else {
#pragma unroll
            for (int j = 0; j < 4; j++) {
                const int jn = bcol + bn0 + 4 * j;
                rb[j] = *(const float4*)(Bm + (size_t)(jn >> 6) * K * 64 +
                                         (size_t)bkr * 64 + (jn & 63));
            }
        }
    }

    for (int kk = 0; kk < K; kk += 32) {
        __syncthreads();
#pragma unroll
        for (int j = 0; j < 4; j++) {
            unsigned h0, l0, h1, l1;
            splitpack(ra[j].x, ra[j].y, h0, l0);
            splitpack(ra[j].z, ra[j].w, h1, l1);
            const int o = arow * 40 + akq + 4 * j;
            *(unsigned*)&AsH[o] = h0; *(unsigned*)&AsH[o + 2] = h1;
            *(unsigned*)&AsL[o] = l0; *(unsigned*)&AsL[o + 2] = l1;
            splitpack(rb[j].x, rb[j].y, h0, l0);
            splitpack(rb[j].z, rb[j].w, h1, l1);
            const int p = bkr * 136 + bn0 + 4 * j;
            *(unsigned*)&BsH[p] = h0; *(unsigned*)&BsH[p + 2] = h1;
            *(unsigned*)&BsL[p] = l0; *(unsigned*)&BsL[p + 2] = l1;
        }
        __syncthreads();

        if (kk + 32 < K) {
            const float* ap = Ab + (size_t)(brow + arow) * K + kk + 32 + akq;
#pragma unroll
            for (int j = 0; j < 4; j++) ra[j] = *(const float4*)(ap + 4 * j);
            if (bmode == 0) {
                const float* bp = Bm + (size_t)(kk + 32 + bkr) * N + bcol + bn0;
#pragma unroll
                for (int j = 0; j < 4; j++) rb[j] = *(const float4*)(bp + 4 * j);
            } else {
#pragma unroll
                for (int j = 0; j < 4; j++) {
                    const int jn = bcol + bn0 + 4 * j;
                    rb[j] = *(const float4*)(Bm + (size_t)(jn >> 6) * K * 64 +
                                             (size_t)(kk + 32 + bkr) * 64 + (jn & 63));
                }
            }
        }

#pragma unroll
        for (int c = 0; c < 2; c++) {
            const int k0 = c * 16;
            unsigned ah[2][4], al[2][4];
#pragma unroll
            for (int mt = 0; mt < 2; mt++) {
                const int m0 = wm * 32 + mt * 16;
                const unsigned off =
                    (unsigned)(((m0 + lr + (ls & 1) * 8) * 40 + k0 + (ls & 2) * 4) * 2);
                ldsm4(ah[mt], aH + off);
                ldsm4(al[mt], aL + off);
            }
#pragma unroll
            for (int nt = 0; nt < 8; nt++) {
                const int n0 = wn * 64 + nt * 8;
                const unsigned off = (unsigned)(((k0 + lb) * 136 + n0) * 2);
                unsigned bh0, bh1, bl0, bl1;
                ldsm2t(bh0, bh1, bH + off);
                ldsm2t(bl0, bl1, bL + off);
#pragma unroll
                for (int mt = 0; mt < 2; mt++) {
                    mma_bf(acc[mt][nt], ah[mt], bh0, bh1);
                    mma_bf(acc[mt][nt], ah[mt], bl0, bl1);
                    mma_bf(acc[mt][nt], al[mt], bh0, bh1);
                }
            }
        }
    }

    const float qs = (cmode == 1 && cId == 0) ? 0.125f : 1.f;
#pragma unroll
    for (int mt = 0; mt < 2; mt++) {
#pragma unroll
        for (int nt = 0; nt < 8; nt++) {
            const int row = brow + wm * 32 + mt * 16 + grp;
            const int col = bcol + wn * 64 + nt * 8 + 2 * tig;
            float b0 = bias ? bias[col] : 0.f, b1 = bias ? bias[col + 1] : 0.f;
            float v00 = (acc[mt][nt][0] + b0) * qs, v01 = (acc[mt][nt][1] + b1) * qs;
            float v10 = (acc[mt][nt][2] + b0) * qs, v11 = (acc[mt][nt][3] + b1) * qs;
            if (relu) {
                v00 = fmaxf(v00, 0.f); v01 = fmaxf(v01, 0.f);
                v10 = fmaxf(v10, 0.f); v11 = fmaxf(v11, 0.f);
            }
            if (cmode == 0) {
                float* Cb = gbuf(cId);
                *(float2*)(Cb + (size_t)row * N + col)       = make_float2(v00, v01);
                *(float2*)(Cb + (size_t)(row + 8) * N + col) = make_float2(v10, v11);
            } else {
                unsigned short *ph, *pl;
                if (cId == 0)      { ph = g_qh; pl = g_ql; }
                else if (cId == 1) { ph = g_kh; pl = g_kl; }
                else               { ph = g_vh; pl = g_vl; }
                const int hh = col >> 6, cc = col & 63;
                const int bb = row >> 11, tt = row & 2047;
                const size_t off = ((size_t)(bb * H_ + hh) * T_ + tt) * 64 + cc;
                unsigned uh, ul;
                splitpack(v00, v01, uh, ul);
                *(unsigned*)&ph[off] = uh; *(unsigned*)&pl[off] = ul;
                splitpack(v10, v11, uh, ul);
                *(unsigned*)&ph[off + 8 * 64] = uh; *(unsigned*)&pl[off + 8 * 64] = ul;
            }
        }
    }
}

// ---------------------------------------------------------------------------
// Tensor-core causal flash attention. 128 q-rows/block, 8 warps x 16 rows.
// smem halfs: QH[128*72] QL | KH KL VH VL [64*72 each]
// ---------------------------------------------------------------------------
#define ATTN_SMEM ((18432 + 4 * 4608) * 2)
__global__ __launch_bounds__(256)
void attn_tc() {
    extern __shared__ __align__(16) unsigned short sh[];
    unsigned short* QH = sh;
    unsigned short* QL = sh + 9216;
    unsigned short* KH = sh + 18432;

    const int qb = blockIdx.x, h = blockIdx.y, b = blockIdx.z;
    const int tid = threadIdx.x, warp = tid >> 5, lane = tid & 31;
    const int grp = lane >> 2, tig = lane & 3, lr = lane & 7;
    const int ls = lane >> 3, phs = ls & 1;
    const size_t pbase = (size_t)(b * H_ + h) * T_ * 64;
    const int rowbase = qb * 128 + warp * 16;
    const unsigned qhB = cvsm(QH), qlB = cvsm(QL), kvB = cvsm(KH);

#pragma unroll
    for (int j = 0; j < 8; j++) {
        const int id = j * 256 + tid;
        const int pl = id >> 10, wi = id & 1023;
        const int r = wi >> 3, c8 = (wi & 7) * 8;
        const unsigned short* src = (pl ? g_ql : g_qh) + pbase + (size_t)(qb * 128 + r) * 64 + c8;
        *(uint4*)((pl ? QL : QH) + r * 72 + c8) = *(const uint4*)src;
    }

    float oacc[8][4];
#pragma unroll
    for (int nt = 0; nt < 8; nt++)
#pragma unroll
        for (int i = 0; i < 4; i++) oacc[nt][i] = 0.f;
    float m0 = -1e30f, m1 = -1e30f, l0 = 0.f, l1 = 0.f;

    const int ntiles = 2 * qb + 2;
    for (int jt = 0; jt < ntiles; jt++) {
        __syncthreads();
#pragma unroll
        for (int j = 0; j < 8; j++) {
            const int id = j * 256 + tid;
            const int pl = id >> 9, wi = id & 511;
            const int r = wi >> 3, c8 = (wi & 7) * 8;
            const unsigned short* src;
            switch (pl) {
                case 0:  src = g_kh; break;
                case 1:  src = g_kl; break;
                case 2:  src = g_vh; break;
                default: src = g_vl; break;
            }
            src += pbase + (size_t)(jt * 64 + r) * 64 + c8;
            *(uint4*)(KH + pl * 4608 + r * 72 + c8) = *(const uint4*)src;
        }
        __syncthreads();
        if (jt * 64 > rowbase + 15) continue;

        // S = Q K^T
        float sacc[8][4];
#pragma unroll
        for (int nt = 0; nt < 8; nt++)
#pragma unroll
            for (int i = 0; i < 4; i++) sacc[nt][i] = 0.f;
#pragma unroll
        for (int kc = 0; kc < 4; kc++) {
            const unsigned aoff =
                (unsigned)(((warp * 16 + lr + (ls & 1) * 8) * 72 + kc * 16 + (ls & 2) * 4) * 2);
            unsigned qh[4], ql[4];
            ldsm4(qh, qhB + aoff);
            ldsm4(ql, qlB + aoff);
#pragma unroll
            for (int nt = 0; nt < 8; nt++) {
                const unsigned ko = kvB +
                    (unsigned)(((nt * 8 + lr) * 72 + kc * 16 + phs * 8) * 2);
                unsigned kh0, kh1, kl0, kl1;
                ldsm2(kh0, kh1, ko);
                ldsm2(kl0, kl1, ko + 4608 * 2);
                mma_bf(sacc[nt], qh, kh0, kh1);
                mma_bf(sacc[nt], qh, kl0, kl1);
                mma_bf(sacc[nt], ql, kh0, kh1);
            }
        }

        // mask + online softmax (rows r0=grp, r1=grp+8)
        const int r0 = rowbase + grp, r1 = r0 + 8;
        if (jt * 64 + 63 > rowbase) {
#pragma unroll
            for (int nt = 0; nt < 8; nt++) {
                const int c0 = jt * 64 + nt * 8 + 2 * tig;
                if (c0     > r0) sacc[nt][0] = -1e30f;
                if (c0 + 1 > r0) sacc[nt][1] = -1e30f;
                if (c0     > r1) sacc[nt][2] = -1e30f;
                if (c0 + 1 > r1) sacc[nt][3] = -1e30f;
            }
        }
        float rm0 = -1e30f, rm1 = -1e30f;
#pragma unroll
        for (int nt = 0; nt < 8; nt++) {
            rm0 = fmaxf(rm0, fmaxf(sacc[nt][0], sacc[nt][1]));
            rm1 = fmaxf(rm1, fmaxf(sacc[nt][2], sacc[nt][3]));
        }
        rm0 = fmaxf(rm0, __shfl_xor_sync(0xffffffffu, rm0, 1));
        rm0 = fmaxf(rm0, __shfl_xor_sync(0xffffffffu, rm0, 2));
        rm1 = fmaxf(rm1, __shfl_xor_sync(0xffffffffu, rm1, 1));
        rm1 = fmaxf(rm1, __shfl_xor_sync(0xffffffffu, rm1, 2));
        const float mn0 = fmaxf(m0, rm0), mn1 = fmaxf(m1, rm1);
        const float al0 = fexpf(m0 - mn0), al1 = fexpf(m1 - mn1);
        float s0 = 0.f, s1 = 0.f;
#pragma unroll
        for (int nt = 0; nt < 8; nt++) {
            sacc[nt][0] = fexpf(sacc[nt][0] - mn0); s0 += sacc[nt][0];
            sacc[nt][1] = fexpf(sacc[nt][1] - mn0); s0 += sacc[nt][1];
            sacc[nt][2] = fexpf(sacc[nt][2] - mn1); s1 += sacc[nt][2];
            sacc[nt][3] = fexpf(sacc[nt][3] - mn1); s1 += sacc[nt][3];
        }
        s0 += __shfl_xor_sync(0xffffffffu, s0, 1);
        s0 += __shfl_xor_sync(0xffffffffu, s0, 2);
        s1 += __shfl_xor_sync(0xffffffffu, s1, 1);
        s1 += __shfl_xor_sync(0xffffffffu, s1, 2);
        l0 = l0 * al0 + s0; m0 = mn0;
        l1 = l1 * al1 + s1; m1 = mn1;
#pragma unroll
        for (int nt = 0; nt < 8; nt++) {
            oacc[nt][0] *= al0; oacc[nt][1] *= al0;
            oacc[nt][2] *= al1; oacc[nt][3] *= al1;
        }

        // O += P V  (P split hi/lo; accumulator layout == A-fragment layout)
#pragma unroll
        for (int kc = 0; kc < 4; kc++) {
            unsigned Ph[4], Pl[4];
            splitpack(sacc[2 * kc][0],     sacc[2 * kc][1],     Ph[0], Pl[0]);
            splitpack(sacc[2 * kc][2],     sacc[2 * kc][3],     Ph[1], Pl[1]);
            splitpack(sacc[2 * kc + 1][0], sacc[2 * kc + 1][1], Ph[2], Pl[2]);
            splitpack(sacc[2 * kc + 1][2], sacc[2 * kc + 1][3], Ph[3], Pl[3]);
#pragma unroll
            for (int nt = 0; nt < 8; nt++) {
                const unsigned vo = kvB +
                    (unsigned)((2 * 4608 + (kc * 16 + lr + phs * 8) * 72 + nt * 8) * 2);
                unsigned vh0, vh1, vl0, vl1;
                ldsm2t(vh0, vh1, vo);
                ldsm2t(vl0, vl1, vo + 4608 * 2);
                mma_bf(oacc[nt], Ph, vh0, vh1);
                mma_bf(oacc[nt], Ph, vl0, vl1);
                mma_bf(oacc[nt], Pl, vh0, vh1);
            }
        }
    }

    const float i0 = 1.f / l0, i1 = 1.f / l1;
    const int t0 = rowbase + grp;
#pragma unroll
    for (int nt = 0; nt < 8; nt++) {
        const int col = h * 64 + nt * 8 + 2 * tig;
        float* p = g_ocat + ((size_t)b * T_ + t0) * D_ + col;
        *(float2*)p             = make_float2(oacc[nt][0] * i0, oacc[nt][1] * i0);
        *(float2*)(p + 8 * D_)  = make_float2(oacc[nt][2] * i1, oacc[nt][3] * i1);
    }
}

// ---------------- LayerNorm ----------------
__device__ __forceinline__ float block_sum(float v, float* red) {
    __syncthreads();
#pragma unroll
    for (int o = 16; o > 0; o >>= 1) v += __shfl_down_sync(0xffffffffu, v, o);
    if ((threadIdx.x & 31) == 0) red[threadIdx.x >> 5] = v;
    __syncthreads();
    if (threadIdx.x < 32) {
        float w = (threadIdx.x < 8) ? red[threadIdx.x] : 0.f;
#pragma unroll
        for (int o = 4; o > 0; o >>= 1) w += __shfl_down_sync(0xffffffffu, w, o);
        if (threadIdx.x == 0) red[0] = w;
    }
    __syncthreads();
    return red[0];
}

__global__ __launch_bounds__(256)
void ln_kernel(int aId, const float* __restrict__ res,
               const float* __restrict__ cbias, const float* __restrict__ g,
               const float* __restrict__ beta,
               float* __restrict__ out_ext, int outId, int addPre) {
    __shared__ float pre[D_];
    __shared__ float red[32];
    const int row = blockIdx.x, tid = threadIdx.x;
    const float* ap = gbuf(aId) + (size_t)row * D_;
    const float* rp = res ? res + (size_t)row * D_ : nullptr;
    float* out = (outId >= 0) ? gbuf(outId) : out_ext;

    float ls = 0.f;
    for (int i = tid; i < D_; i += 256) {
        float v = ap[i];
        if (rp)    v += rp[i];
        if (cbias) v += cbias[i];
        pre[i] = v;
        ls += v;
    }
    const float mean = block_sum(ls, red) * (1.f / D_);
    float lv = 0.f;
    for (int i = tid; i < D_; i += 256) {
        const float d = pre[i] - mean;
        lv += d * d;
    }
    const float var = block_sum(lv, red) * (1.f / D_);
    const float rstd = rsqrtf(var + 1e-5f);
    for (int i = tid; i < D_; i += 256) {
        const float p = pre[i];
        out[(size_t)row * D_ + i] = (p - mean) * rstd * g[i] + beta[i] + (addPre ? p : 0.f);
    }
}

// ---------------- launcher ----------------
extern "C" void kernel_launch(void* const* d_in, const int* in_sizes, int n_in,
                              void* d_out, int out_size) {
    const float* x    = (const float*)d_in[0];
    const float* Wq   = (const float*)d_in[1];
    const float* bq   = (const float*)d_in[2];
    const float* Wk   = (const float*)d_in[3];
    const float* bk   = (const float*)d_in[4];
    const float* Wv   = (const float*)d_in[5];
    const float* bv   = (const float*)d_in[6];
    const float* Wo   = (const float*)d_in[7];
    const float* bo   = (const float*)d_in[8];
    const float* ln1g = (const float*)d_in[9];
    const float* ln1b = (const float*)d_in[10];
    const float* W1   = (const float*)d_in[11];
    const float* b1   = (const float*)d_in[12];
    const float* W2   = (const float*)d_in[13];
    const float* b2   = (const float*)d_in[14];
    const float* ln2g = (const float*)d_in[15];
    const float* ln2b = (const float*)d_in[16];
    float* out = (float*)d_out;

    dim3 gN(D_ / 128, MBT / 128);
    // QKV -> bf16 hi/lo planes (Q pre-scaled by 1/8)
    gemm_bf3<<<gN, 256>>>(x, -1, Wq, bq, 0, D_, D_, 1, 1, 0);
    gemm_bf3<<<gN, 256>>>(x, -1, Wk, bk, 1, D_, D_, 1, 1, 0);
    gemm_bf3<<<gN, 256>>>(x, -1, Wv, bv, 2, D_, D_, 1, 1, 0);

    cudaFuncSetAttribute(attn_tc, cudaFuncAttributeMaxDynamicSharedMemorySize, ATTN_SMEM);
    attn_tc<<<dim3(T_ / 128, H_, B_), 256, ATTN_SMEM>>>();

    gemm_bf3<<<gN, 256>>>(nullptr, ID_OCAT, Wo, nullptr, ID_ATTN, D_, D_, 0, 0, 0);
    ln_kernel<<<MBT, 256>>>(ID_ATTN, x, bo, ln1g, ln1b, nullptr, ID_H, 0);
    gemm_bf3<<<dim3(NF_ / 128, MBT / 128), 256>>>(nullptr, ID_H, W1, b1, ID_F, NF_, D_, 0, 0, 1);
    gemm_bf3<<<gN, 256>>>(nullptr, ID_F, W2, b2, ID_Y, D_, NF_, 0, 0, 0);
    ln_kernel<<<MBT, 256>>>(ID_Y, nullptr, nullptr, ln2g, ln2b, out, -1, 1);
}

// round 7
// speedup vs baseline: 2.3131x; 1.1913x over previous
#include <cuda_runtime.h>
#include <cuda_bf16.h>
#include <math.h>
#include <stdint.h>

#define B_   2
#define T_   2048
#define D_   1024
#define H_   16
#define NF_  4096
#define MBT  (B_ * T_)
#define NPL ((size_t)B_ * H_ * T_ * 64)

typedef unsigned short ush;

// ---------------- global scratch (no allocation allowed) ----------------
__device__ __align__(16) ush g_qh[NPL], g_ql[NPL];
__device__ __align__(16) ush g_kh[NPL], g_kl[NPL];
__device__ __align__(16) ush g_vh[NPL], g_vl[NPL];
__device__ __align__(16) ush g_och[(size_t)MBT * D_], g_ocl[(size_t)MBT * D_];
__device__ __align__(16) ush g_hh[(size_t)MBT * D_],  g_hl[(size_t)MBT * D_];
__device__ __align__(16) ush g_fh[(size_t)MBT * NF_], g_fl[(size_t)MBT * NF_];
__device__ __align__(16) ush g_xh[(size_t)MBT * D_],  g_xl[(size_t)MBT * D_];
__device__ __align__(16) ush g_wqh[(size_t)D_ * 3072], g_wql[(size_t)D_ * 3072];
__device__ __align__(16) ush g_woh[(size_t)D_ * D_],  g_wol[(size_t)D_ * D_];
__device__ __align__(16) ush g_w1h[(size_t)D_ * NF_], g_w1l[(size_t)D_ * NF_];
__device__ __align__(16) ush g_w2h[(size_t)NF_ * D_], g_w2l[(size_t)NF_ * D_];
__device__ float g_attn[(size_t)MBT * D_];
__device__ float g_y[(size_t)MBT * D_];
__device__ float g_bqkv[3072];

__device__ __forceinline__ void pbuf(int id, ush*& ph, ush*& pl) {
    switch (id) {
        case 0:  ph = g_qh;  pl = g_ql;  break;
        case 1:  ph = g_kh;  pl = g_kl;  break;
        case 2:  ph = g_vh;  pl = g_vl;  break;
        case 3:  ph = g_och; pl = g_ocl; break;
        case 4:  ph = g_hh;  pl = g_hl;  break;
        case 5:  ph = g_fh;  pl = g_fl;  break;
        case 6:  ph = g_xh;  pl = g_xl;  break;
        case 7:  ph = g_wqh; pl = g_wql; break;
        case 8:  ph = g_woh; pl = g_wol; break;
        case 9:  ph = g_w1h; pl = g_w1l; break;
        default: ph = g_w2h; pl = g_w2l; break;
    }
}

// ---------------- helpers ----------------
__device__ __forceinline__ void splitpack(float x, float y, unsigned& hi, unsigned& lo) {
    __nv_bfloat16 xh = __float2bfloat16(x);
    __nv_bfloat16 yh = __float2bfloat16(y);
    __nv_bfloat16 xl = __float2bfloat16(x - __bfloat162float(xh));
    __nv_bfloat16 yl = __float2bfloat16(y - __bfloat162float(yh));
    hi = (unsigned)__bfloat16_as_ushort(xh) | ((unsigned)__bfloat16_as_ushort(yh) << 16);
    lo = (unsigned)__bfloat16_as_ushort(xl) | ((unsigned)__bfloat16_as_ushort(yl) << 16);
}
__device__ __forceinline__ unsigned cvsm(const void* p) {
    return (unsigned)__cvta_generic_to_shared(p);
}
__device__ __forceinline__ void ldsm4(unsigned* r, unsigned a) {
    asm volatile("ldmatrix.sync.aligned.m8n8.x4.shared.b16 {%0,%1,%2,%3}, [%4];"
                 : "=r"(r[0]), "=r"(r[1]), "=r"(r[2]), "=r"(r[3]) : "r"(a));
}
__device__ __forceinline__ void ldsm4t(unsigned* r, unsigned a) {
    asm volatile("ldmatrix.sync.aligned.m8n8.x4.trans.shared.b16 {%0,%1,%2,%3}, [%4];"
                 : "=r"(r[0]), "=r"(r[1]), "=r"(r[2]), "=r"(r[3]) : "r"(a));
}
__device__ __forceinline__ void ldsm2(unsigned& r0, unsigned& r1, unsigned a) {
    asm volatile("ldmatrix.sync.aligned.m8n8.x2.shared.b16 {%0,%1}, [%2];"
                 : "=r"(r0), "=r"(r1) : "r"(a));
}
__device__ __forceinline__ void ldsm2t(unsigned& r0, unsigned& r1, unsigned a) {
    asm volatile("ldmatrix.sync.aligned.m8n8.x2.trans.shared.b16 {%0,%1}, [%2];"
                 : "=r"(r0), "=r"(r1) : "r"(a));
}
__device__ __forceinline__ void mma_bf(float* c, const unsigned* a, unsigned b0, unsigned b1) {
    asm volatile(
        "mma.sync.aligned.m16n8k16.row.col.f32.bf16.bf16.f32 "
        "{%0,%1,%2,%3}, {%4,%5,%6,%7}, {%8,%9}, {%0,%1,%2,%3};\n"
        : "+f"(c[0]), "+f"(c[1]), "+f"(c[2]), "+f"(c[3])
        : "r"(a[0]), "r"(a[1]), "r"(a[2]), "r"(a[3]), "r"(b0), "r"(b1));
}
#define CPA16(dst, src) \
    asm volatile("cp.async.cg.shared.global [%0], [%1], 16;" :: "r"(dst), "l"(src))
#define CPA_COMMIT() asm volatile("cp.async.commit_group;")
#define CPA_WAIT1()  asm volatile("cp.async.wait_group 1;")
#define CPA_WAIT0()  asm volatile("cp.async.wait_group 0;")

__device__ __forceinline__ float fexpf(float x) {
    x = fmaxf(x, -87.0f);
    float t = fmaf(x, 1.4426950408889634f, 12582912.0f);
    int   ni = __float_as_int(t) - 0x4B400000;
    float n  = t - 12582912.0f;
    float f  = fmaf(x, 1.4426950408889634f, -n);
    float p = 1.333355626e-3f;
    p = fmaf(p, f, 9.618129633e-3f);
    p = fmaf(p, f, 5.550410866e-2f);
    p = fmaf(p, f, 2.402265069e-1f);
    p = fmaf(p, f, 6.931471806e-1f);
    p = fmaf(p, f, 1.0f);
    return p * __int_as_float((ni + 127) << 23);
}

// ---------------- conversion kernels ----------------
__global__ __launch_bounds__(256)
void cvt_plane(const float* __restrict__ src, int pid, int npairs) {
    int i = blockIdx.x * 256 + threadIdx.x;
    if (i >= npairs) return;
    ush *ph, *pl; pbuf(pid, ph, pl);
    float2 v = *(const float2*)(src + (size_t)2 * i);
    unsigned h, l; splitpack(v.x, v.y, h, l);
    *(unsigned*)&ph[(size_t)2 * i] = h;
    *(unsigned*)&pl[(size_t)2 * i] = l;
}

// Wq/Wk/Wv [H,D,64] -> combined planes [D, 3072], col = which*1024 + h*64 + c
__global__ __launch_bounds__(256)
void cvt_qkvw(const float* __restrict__ Wq, const float* __restrict__ Wk,
              const float* __restrict__ Wv) {
    int idx = blockIdx.x * 256 + threadIdx.x;     // over 1024*1536 pairs
    if (idx >= 1024 * 1536) return;
    const int d = idx / 1536, j3 = (idx % 1536) * 2;
    const int which = j3 >> 10, j = j3 & 1023, h = j >> 6, c = j & 63;
    const float* W = (which == 0) ? Wq : ((which == 1) ? Wk : Wv);
    const size_t s = (size_t)h * 65536 + (size_t)d * 64 + c;
    unsigned hh, ll; splitpack(W[s], W[s + 1], hh, ll);
    *(unsigned*)&g_wqh[(size_t)d * 3072 + j3] = hh;
    *(unsigned*)&g_wql[(size_t)d * 3072 + j3] = ll;
}

__global__ __launch_bounds__(256)
void cvt_bias(const float* __restrict__ bq, const float* __restrict__ bk,
              const float* __restrict__ bv) {
    int i = blockIdx.x * 256 + threadIdx.x;
    if (i >= 3072) return;
    const int which = i >> 10, j = i & 1023;
    const float* s = (which == 0) ? bq : ((which == 1) ? bk : bv);
    g_bqkv[i] = s[j];
}

// ---------------------------------------------------------------------------
// Pure-bf16-plane GEMM, 3-term split, cp.async 2-stage pipeline.
// BM=128 BN=128 BK=32, 256 threads, 8 warps (4x2), warp tile 32x64.
// smem halfs per stage: Ah[128*40] Al | Bh[32*136] Bl  (18944 halfs/stage)
// outMode: 0 fp32 (outId 0=g_attn, 1=g_y); 1 qkv scatter; 2 planes pbuf(outId)
// ---------------------------------------------------------------------------
#define GSTG 18944
#define GEMM_SMEM (2 * GSTG * 2)

__device__ __forceinline__ void gemm_issue(unsigned smB, int tid,
    const ush* __restrict__ Ah, const ush* __restrict__ Al,
    const ush* __restrict__ Bh, const ush* __restrict__ Bl,
    int brow, int bcol, int kk, int K, int N) {
#pragma unroll
    for (int j = 0; j < 8; j++) {
        const int id = j * 256 + tid;
        if (id < 1024) {
            const ush* sp = (id < 512) ? Ah : Al;
            const int c = id & 511, row = c >> 2, ch = c & 3;
            const ush* s = sp + (size_t)(brow + row) * K + kk + ch * 8;
            const unsigned dst = smB + (unsigned)(((id < 512 ? 0 : 5120) + row * 40 + ch * 8) * 2);
            CPA16(dst, s);
        } else {
            const ush* sp = (id < 1536) ? Bh : Bl;
            const int c = id & 511, row = c >> 4, ch = c & 15;
            const ush* s = sp + (size_t)(kk + row) * N + bcol + ch * 8;
            const unsigned dst = smB + (unsigned)((10240 + (id < 1536 ? 0 : 4352) + row * 136 + ch * 8) * 2);
            CPA16(dst, s);
        }
    }
}

__global__ __launch_bounds__(256, 2)
void gemm_bf(int aPid, int bPid, const float* __restrict__ bias, int qkvBias,
             int outMode, int outId, int N, int K, int relu)
{
    extern __shared__ __align__(16) ush gsm[];
    const unsigned smB = cvsm(gsm);

    ush *Ah, *Al, *Bh, *Bl;
    pbuf(aPid, Ah, Al);
    pbuf(bPid, Bh, Bl);

    const int tid = threadIdx.x;
    const int brow = blockIdx.y * 128, bcol = blockIdx.x * 128;
    const int warp = tid >> 5, lane = tid & 31;
    const int wm = warp >> 1, wn = warp & 1;
    const int grp = lane >> 2, tig = lane & 3;
    const int lr = lane & 7, ls = lane >> 3;

    float acc[2][8][4];
#pragma unroll
    for (int mt = 0; mt < 2; mt++)
#pragma unroll
        for (int nt = 0; nt < 8; nt++)
#pragma unroll
            for (int i = 0; i < 4; i++) acc[mt][nt][i] = 0.f;

    const int ntl = K / 32;
    gemm_issue(smB, tid, Ah, Al, Bh, Bl, brow, bcol, 0, K, N);
    CPA_COMMIT();

    for (int t = 0; t < ntl; t++) {
        if (t > 0) __syncthreads();
        if (t + 1 < ntl) {
            gemm_issue(smB + (unsigned)(((t + 1) & 1) * GSTG * 2), tid,
                       Ah, Al, Bh, Bl, brow, bcol, (t + 1) * 32, K, N);
            CPA_COMMIT();
            CPA_WAIT1();
        } else {
            CPA_WAIT0();
        }
        __syncthreads();

        const unsigned sb = smB + (unsigned)((t & 1) * GSTG * 2);
#pragma unroll
        for (int kc = 0; kc < 2; kc++) {
            unsigned ah[2][4], al[2][4];
#pragma unroll
            for (int mt = 0; mt < 2; mt++) {
                const unsigned ao = sb + (unsigned)(((wm * 32 + mt * 16 + lr + (ls & 1) * 8) * 40
                                                    + kc * 16 + (ls & 2) * 4) * 2);
                ldsm4(ah[mt], ao);
                ldsm4(al[mt], ao + 5120 * 2);
            }
#pragma unroll
            for (int nt2 = 0; nt2 < 4; nt2++) {
                const int row = kc * 16 + (ls & 1) * 8 + lr;
                const int col = wn * 64 + nt2 * 16 + (ls >> 1) * 8;
                const unsigned bo = sb + (unsigned)((10240 + row * 136 + col) * 2);
                unsigned bh[4], bl[4];
                ldsm4t(bh, bo);
                ldsm4t(bl, bo + 4352 * 2);
#pragma unroll
                for (int hf = 0; hf < 2; hf++) {
                    const int nt = 2 * nt2 + hf;
#pragma unroll
                    for (int mt = 0; mt < 2; mt++) {
                        mma_bf(acc[mt][nt], ah[mt], bh[2 * hf], bh[2 * hf + 1]);
                        mma_bf(acc[mt][nt], ah[mt], bl[2 * hf], bl[2 * hf + 1]);
                        mma_bf(acc[mt][nt], al[mt], bh[2 * hf], bh[2 * hf + 1]);
                    }
                }
            }
        }
    }

    // epilogue
#pragma unroll
    for (int mt = 0; mt < 2; mt++) {
#pragma unroll
        for (int nt = 0; nt < 8; nt++) {
            const int row = brow + wm * 32 + mt * 16 + grp;
            const int col = bcol + wn * 64 + nt * 8 + 2 * tig;
            float b0 = 0.f, b1 = 0.f;
            if (qkvBias)   { b0 = g_bqkv[col]; b1 = g_bqkv[col + 1]; }
            else if (bias) { b0 = bias[col];   b1 = bias[col + 1]; }
            float v00 = acc[mt][nt][0] + b0, v01 = acc[mt][nt][1] + b1;
            float v10 = acc[mt][nt][2] + b0, v11 = acc[mt][nt][3] + b1;
            if (relu) {
                v00 = fmaxf(v00, 0.f); v01 = fmaxf(v01, 0.f);
                v10 = fmaxf(v10, 0.f); v11 = fmaxf(v11, 0.f);
            }
            if (outMode == 0) {
                float* C = (outId == 0) ? g_attn : g_y;
                *(float2*)(C + (size_t)row * N + col)       = make_float2(v00, v01);
                *(float2*)(C + (size_t)(row + 8) * N + col) = make_float2(v10, v11);
            } else if (outMode == 1) {
                const int which = col >> 10;
                if (which == 0) { v00 *= 0.125f; v01 *= 0.125f; v10 *= 0.125f; v11 *= 0.125f; }
                ush *ph, *pl; pbuf(which, ph, pl);
                const int hh = (col >> 6) & 15, cc = col & 63;
                const int bb = row >> 11, tt = row & 2047;
                const size_t off = ((size_t)(bb * H_ + hh) * T_ + tt) * 64 + cc;
                unsigned uh, ul;
                splitpack(v00, v01, uh, ul);
                *(unsigned*)&ph[off] = uh; *(unsigned*)&pl[off] = ul;
                splitpack(v10, v11, uh, ul);
                *(unsigned*)&ph[off + 8 * 64] = uh; *(unsigned*)&pl[off + 8 * 64] = ul;
            } else {
                ush *ph, *pl; pbuf(outId, ph, pl);
                const size_t off = (size_t)row * N + col;
                unsigned uh, ul;
                splitpack(v00, v01, uh, ul);
                *(unsigned*)&ph[off] = uh; *(unsigned*)&pl[off] = ul;
                splitpack(v10, v11, uh, ul);
                *(unsigned*)&ph[off + (size_t)8 * N] = uh;
                *(unsigned*)&pl[off + (size_t)8 * N] = ul;
            }
        }
    }
}

// ---------------------------------------------------------------------------
// Tensor-core causal flash attention (as round 6, epilogue -> ocat planes)
// ---------------------------------------------------------------------------
#define ATTN_SMEM ((18432 + 4 * 4608) * 2)
__global__ __launch_bounds__(256)
void attn_tc() {
    extern __shared__ __align__(16) ush sh[];
    ush* QH = sh;
    ush* QL = sh + 9216;
    ush* KH = sh + 18432;

    const int qb = blockIdx.x, h = blockIdx.y, b = blockIdx.z;
    const int tid = threadIdx.x, warp = tid >> 5, lane = tid & 31;
    const int grp = lane >> 2, tig = lane & 3, lr = lane & 7;
    const int ls = lane >> 3, phs = ls & 1;
    const size_t pbase = (size_t)(b * H_ + h) * T_ * 64;
    const int rowbase = qb * 128 + warp * 16;
    const unsigned qhB = cvsm(QH), qlB = cvsm(QL), kvB = cvsm(KH);

#pragma unroll
    for (int j = 0; j < 8; j++) {
        const int id = j * 256 + tid;
        const int pl = id >> 10, wi = id & 1023;
        const int r = wi >> 3, c8 = (wi & 7) * 8;
        const ush* src = (pl ? g_ql : g_qh) + pbase + (size_t)(qb * 128 + r) * 64 + c8;
        *(uint4*)((pl ? QL : QH) + r * 72 + c8) = *(const uint4*)src;
    }

    float oacc[8][4];
#pragma unroll
    for (int nt = 0; nt < 8; nt++)
#pragma unroll
        for (int i = 0; i < 4; i++) oacc[nt][i] = 0.f;
    float m0 = -1e30f, m1 = -1e30f, l0 = 0.f, l1 = 0.f;

    const int ntiles = 2 * qb + 2;
    for (int jt = 0; jt < ntiles; jt++) {
        __syncthreads();
#pragma unroll
        for (int j = 0; j < 8; j++) {
            const int id = j * 256 + tid;
            const int pl = id >> 9, wi = id & 511;
            const int r = wi >> 3, c8 = (wi & 7) * 8;
            const ush* src;
            switch (pl) {
                case 0:  src = g_kh; break;
                case 1:  src = g_kl; break;
                case 2:  src = g_vh; break;
                default: src = g_vl; break;
            }
            src += pbase + (size_t)(jt * 64 + r) * 64 + c8;
            *(uint4*)(KH + pl * 4608 + r * 72 + c8) = *(const uint4*)src;
        }
        __syncthreads();
        if (jt * 64 > rowbase + 15) continue;

        float sacc[8][4];
#pragma unroll
        for (int nt = 0; nt < 8; nt++)
#pragma unroll
            for (int i = 0; i < 4; i++) sacc[nt][i] = 0.f;
#pragma unroll
        for (int kc = 0; kc < 4; kc++) {
            const unsigned aoff =
                (unsigned)(((warp * 16 + lr + (ls & 1) * 8) * 72 + kc * 16 + (ls & 2) * 4) * 2);
            unsigned qh[4], ql[4];
            ldsm4(qh, qhB + aoff);
            ldsm4(ql, qlB + aoff);
#pragma unroll
            for (int nt = 0; nt < 8; nt++) {
                const unsigned ko = kvB +
                    (unsigned)(((nt * 8 + lr) * 72 + kc * 16 + phs * 8) * 2);
                unsigned kh0, kh1, kl0, kl1;
                ldsm2(kh0, kh1, ko);
                ldsm2(kl0, kl1, ko + 4608 * 2);
                mma_bf(sacc[nt], qh, kh0, kh1);
                mma_bf(sacc[nt], qh, kl0, kl1);
                mma_bf(sacc[nt], ql, kh0, kh1);
            }
        }

        const int r0 = rowbase + grp, r1 = r0 + 8;
        if (jt * 64 + 63 > rowbase) {
#pragma unroll
            for (int nt = 0; nt < 8; nt++) {
                const int c0 = jt * 64 + nt * 8 + 2 * tig;
                if (c0     > r0) sacc[nt][0] = -1e30f;
                if (c0 + 1 > r0) sacc[nt][1] = -1e30f;
                if (c0     > r1) sacc[nt][2] = -1e30f;
                if (c0 + 1 > r1) sacc[nt][3] = -1e30f;
            }
        }
        float rm0 = -1e30f, rm1 = -1e30f;
#pragma unroll
        for (int nt = 0; nt < 8; nt++) {
            rm0 = fmaxf(rm0, fmaxf(sacc[nt][0], sacc[nt][1]));
            rm1 = fmaxf(rm1, fmaxf(sacc[nt][2], sacc[nt][3]));
        }
        rm0 = fmaxf(rm0, __shfl_xor_sync(0xffffffffu, rm0, 1));
        rm0 = fmaxf(rm0, __shfl_xor_sync(0xffffffffu, rm0, 2));
        rm1 = fmaxf(rm1, __shfl_xor_sync(0xffffffffu, rm1, 1));
        rm1 = fmaxf(rm1, __shfl_xor_sync(0xffffffffu, rm1, 2));
        const float mn0 = fmaxf(m0, rm0), mn1 = fmaxf(m1, rm1);
        const float al0 = fexpf(m0 - mn0), al1 = fexpf(m1 - mn1);
        float s0 = 0.f, s1 = 0.f;
#pragma unroll
        for (int nt = 0; nt < 8; nt++) {
            sacc[nt][0] = fexpf(sacc[nt][0] - mn0); s0 += sacc[nt][0];
            sacc[nt][1] = fexpf(sacc[nt][1] - mn0); s0 += sacc[nt][1];
            sacc[nt][2] = fexpf(sacc[nt][2] - mn1); s1 += sacc[nt][2];
            sacc[nt][3] = fexpf(sacc[nt][3] - mn1); s1 += sacc[nt][3];
        }
        s0 += __shfl_xor_sync(0xffffffffu, s0, 1);
        s0 += __shfl_xor_sync(0xffffffffu, s0, 2);
        s1 += __shfl_xor_sync(0xffffffffu, s1, 1);
        s1 += __shfl_xor_sync(0xffffffffu, s1, 2);
        l0 = l0 * al0 + s0; m0 = mn0;
        l1 = l1 * al1 + s1; m1 = mn1;
#pragma unroll
        for (int nt = 0; nt < 8; nt++) {
            oacc[nt][0] *= al0; oacc[nt][1] *= al0;
            oacc[nt][2] *= al1; oacc[nt][3] *= al1;
        }

#pragma unroll
        for (int kc = 0; kc < 4; kc++) {
            unsigned Ph[4], Pl[4];
            splitpack(sacc[2 * kc][0],     sacc[2 * kc][1],     Ph[0], Pl[0]);
            splitpack(sacc[2 * kc][2],     sacc[2 * kc][3],     Ph[1], Pl[1]);
            splitpack(sacc[2 * kc + 1][0], sacc[2 * kc + 1][1], Ph[2], Pl[2]);
            splitpack(sacc[2 * kc + 1][2], sacc[2 * kc + 1][3], Ph[3], Pl[3]);
#pragma unroll
            for (int nt = 0; nt < 8; nt++) {
                const unsigned vo = kvB +
                    (unsigned)((2 * 4608 + (kc * 16 + lr + phs * 8) * 72 + nt * 8) * 2);
                unsigned vh0, vh1, vl0, vl1;
                ldsm2t(vh0, vh1, vo);
                ldsm2t(vl0, vl1, vo + 4608 * 2);
                mma_bf(oacc[nt], Ph, vh0, vh1);
                mma_bf(oacc[nt], Ph, vl0, vl1);
                mma_bf(oacc[nt], Pl, vh0, vh1);
            }
        }
    }

    const float i0 = 1.f / l0, i1 = 1.f / l1;
    const int t0 = rowbase + grp;
#pragma unroll
    for (int nt = 0; nt < 8; nt++) {
        const int col = h * 64 + nt * 8 + 2 * tig;
        const size_t off = ((size_t)b * T_ + t0) * D_ + col;
        unsigned uh, ul;
        splitpack(oacc[nt][0] * i0, oacc[nt][1] * i0, uh, ul);
        *(unsigned*)&g_och[off] = uh; *(unsigned*)&g_ocl[off] = ul;
        splitpack(oacc[nt][2] * i1, oacc[nt][3] * i1, uh, ul);
        *(unsigned*)&g_och[off + (size_t)8 * D_] = uh;
        *(unsigned*)&g_ocl[off + (size_t)8 * D_] = ul;
    }
}

// ---------------- LayerNorm ----------------
__device__ __forceinline__ float block_sum(float v, float* red) {
    __syncthreads();
#pragma unroll
    for (int o = 16; o > 0; o >>= 1) v += __shfl_down_sync(0xffffffffu, v, o);
    if ((threadIdx.x & 31) == 0) red[threadIdx.x >> 5] = v;
    __syncthreads();
    if (threadIdx.x < 32) {
        float w = (threadIdx.x < 8) ? red[threadIdx.x] : 0.f;
#pragma unroll
        for (int o = 4; o > 0; o >>= 1) w += __shfl_down_sync(0xffffffffu, w, o);
        if (threadIdx.x == 0) red[0] = w;
    }
    __syncthreads();
    return red[0];
}

// aId: 0 = g_attn, 1 = g_y. Output: planes pbuf(outPid) if outPid>=0 else fp32 out_ext.
__global__ __launch_bounds__(256)
void ln_kernel(int aId, const float* __restrict__ res,
               const float* __restrict__ cbias, const float* __restrict__ g,
               const float* __restrict__ beta,
               float* __restrict__ out_ext, int outPid, int addPre) {
    __shared__ float pre[D_];
    __shared__ float red[32];
    const int row = blockIdx.x, tid = threadIdx.x;
    const float* ap = ((aId == 0) ? g_attn : g_y) + (size_t)row * D_;
    const float* rp = res ? res + (size_t)row * D_ : nullptr;

    float ls = 0.f;
    for (int i = tid * 2; i < D_; i += 512) {
        float2 a2 = *(const float2*)(ap + i);
        float v0 = a2.x, v1 = a2.y;
        if (rp)    { float2 r2 = *(const float2*)(rp + i);    v0 += r2.x; v1 += r2.y; }
        if (cbias) { float2 c2 = *(const float2*)(cbias + i); v0 += c2.x; v1 += c2.y; }
        pre[i] = v0; pre[i + 1] = v1;
        ls += v0 + v1;
    }
    const float mean = block_sum(ls, red) * (1.f / D_);
    float lv = 0.f;
    for (int i = tid * 2; i < D_; i += 512) {
        const float d0 = pre[i] - mean, d1 = pre[i + 1] - mean;
        lv += d0 * d0 + d1 * d1;
    }
    const float var = block_sum(lv, red) * (1.f / D_);
    const float rstd = rsqrtf(var + 1e-5f);
    for (int i = tid * 2; i < D_; i += 512) {
        const float p0 = pre[i], p1 = pre[i + 1];
        float z0 = (p0 - mean) * rstd * g[i]     + beta[i]     + (addPre ? p0 : 0.f);
        float z1 = (p1 - mean) * rstd * g[i + 1] + beta[i + 1] + (addPre ? p1 : 0.f);
        if (outPid >= 0) {
            ush *ph, *pl; pbuf(outPid, ph, pl);
            unsigned uh, ul; splitpack(z0, z1, uh, ul);
            *(unsigned*)&ph[(size_t)row * D_ + i] = uh;
            *(unsigned*)&pl[(size_t)row * D_ + i] = ul;
        } else {
            *(float2*)(out_ext + (size_t)row * D_ + i) = make_float2(z0, z1);
        }
    }
}

// ---------------- launcher ----------------
extern "C" void kernel_launch(void* const* d_in, const int* in_sizes, int n_in,
                              void* d_out, int out_size) {
    const float* x    = (const float*)d_in[0];
    const float* Wq   = (const float*)d_in[1];
    const float* bq   = (const float*)d_in[2];
    const float* Wk   = (const float*)d_in[3];
    const float* bk   = (const float*)d_in[4];
    const float* Wv   = (const float*)d_in[5];
    const float* bv   = (const float*)d_in[6];
    const float* Wo   = (const float*)d_in[7];
    const float* bo   = (const float*)d_in[8];
    const float* ln1g = (const float*)d_in[9];
    const float* ln1b = (const float*)d_in[10];
    const float* W1   = (const float*)d_in[11];
    const float* b1   = (const float*)d_in[12];
    const float* W2   = (const float*)d_in[13];
    const float* b2   = (const float*)d_in[14];
    const float* ln2g = (const float*)d_in[15];
    const float* ln2b = (const float*)d_in[16];
    float* out = (float*)d_out;

    // conversions (once per call; cheap)
    cvt_bias<<<12, 256>>>(bq, bk, bv);
    cvt_qkvw<<<6144, 256>>>(Wq, Wk, Wv);
    cvt_plane<<<8192, 256>>>(x,  6, MBT * D_ / 2);
    cvt_plane<<<2048, 256>>>(Wo, 8, D_ * D_ / 2);
    cvt_plane<<<8192, 256>>>(W1, 9, D_ * NF_ / 2);
    cvt_plane<<<8192, 256>>>(W2, 10, NF_ * D_ / 2);

    cudaFuncSetAttribute(gemm_bf, cudaFuncAttributeMaxDynamicSharedMemorySize, GEMM_SMEM);
    cudaFuncSetAttribute(attn_tc, cudaFuncAttributeMaxDynamicSharedMemorySize, ATTN_SMEM);

    // QKV fused: [4096,1024] @ [1024,3072] -> q/k/v planes (q pre-scaled)
    gemm_bf<<<dim3(3072 / 128, MBT / 128), 256, GEMM_SMEM>>>(6, 7, nullptr, 1, 1, 0, 3072, D_, 0);

    attn_tc<<<dim3(T_ / 128, H_, B_), 256, ATTN_SMEM>>>();

    // O-proj -> fp32 g_attn
    gemm_bf<<<dim3(D_ / 128, MBT / 128), 256, GEMM_SMEM>>>(3, 8, nullptr, 0, 0, 0, D_, D_, 0);

    // LN1 -> h planes
    ln_kernel<<<MBT, 256>>>(0, x, bo, ln1g, ln1b, nullptr, 4, 0);

    // FFN1 -> f planes (relu)
    gemm_bf<<<dim3(NF_ / 128, MBT / 128), 256, GEMM_SMEM>>>(4, 9, b1, 0, 2, 5, NF_, D_, 1);

    // FFN2 -> fp32 g_y
    gemm_bf<<<dim3(D_ / 128, MBT / 128), 256, GEMM_SMEM>>>(5, 10, b2, 0, 0, 1, D_, NF_, 0);

    // LN2 -> out (+y)
    ln_kernel<<<MBT, 256>>>(1, nullptr, nullptr, ln2g, ln2b, out, -1, 1);
}

// round 8
// speedup vs baseline: 2.3209x; 1.0034x over previous
#include <cuda_runtime.h>
#include <cuda_bf16.h>
#include <math.h>
#include <stdint.h>

#define B_   2
#define T_   2048
#define D_   1024
#define H_   16
#define NF_  4096
#define MBT  (B_ * T_)
#define NPL ((size_t)B_ * H_ * T_ * 64)

typedef unsigned short ush;

// ---------------- global scratch (no allocation allowed) ----------------
__device__ __align__(16) ush g_qh[NPL], g_ql[NPL];
__device__ __align__(16) ush g_kh[NPL], g_kl[NPL];
__device__ __align__(16) ush g_vh[NPL], g_vl[NPL];
__device__ __align__(16) ush g_och[(size_t)MBT * D_], g_ocl[(size_t)MBT * D_];
__device__ __align__(16) ush g_hh[(size_t)MBT * D_],  g_hl[(size_t)MBT * D_];
__device__ __align__(16) ush g_fh[(size_t)MBT * NF_], g_fl[(size_t)MBT * NF_];
__device__ __align__(16) ush g_xh[(size_t)MBT * D_],  g_xl[(size_t)MBT * D_];
__device__ __align__(16) ush g_wqh[(size_t)D_ * 3072], g_wql[(size_t)D_ * 3072];
__device__ __align__(16) ush g_woh[(size_t)D_ * D_],  g_wol[(size_t)D_ * D_];
__device__ __align__(16) ush g_w1h[(size_t)D_ * NF_], g_w1l[(size_t)D_ * NF_];
__device__ __align__(16) ush g_w2h[(size_t)NF_ * D_], g_w2l[(size_t)NF_ * D_];
__device__ float g_attn[(size_t)MBT * D_];
__device__ float g_y[(size_t)MBT * D_];
__device__ float g_bqkv[3072];

__device__ __forceinline__ void pbuf(int id, ush*& ph, ush*& pl) {
    switch (id) {
        case 0:  ph = g_qh;  pl = g_ql;  break;
        case 1:  ph = g_kh;  pl = g_kl;  break;
        case 2:  ph = g_vh;  pl = g_vl;  break;
        case 3:  ph = g_och; pl = g_ocl; break;
        case 4:  ph = g_hh;  pl = g_hl;  break;
        case 5:  ph = g_fh;  pl = g_fl;  break;
        case 6:  ph = g_xh;  pl = g_xl;  break;
        case 7:  ph = g_wqh; pl = g_wql; break;
        case 8:  ph = g_woh; pl = g_wol; break;
        case 9:  ph = g_w1h; pl = g_w1l; break;
        default: ph = g_w2h; pl = g_w2l; break;
    }
}

// ---------------- helpers ----------------
__device__ __forceinline__ void splitpack(float x, float y, unsigned& hi, unsigned& lo) {
    __nv_bfloat16 xh = __float2bfloat16(x);
    __nv_bfloat16 yh = __float2bfloat16(y);
    __nv_bfloat16 xl = __float2bfloat16(x - __bfloat162float(xh));
    __nv_bfloat16 yl = __float2bfloat16(y - __bfloat162float(yh));
    hi = (unsigned)__bfloat16_as_ushort(xh) | ((unsigned)__bfloat16_as_ushort(yh) << 16);
    lo = (unsigned)__bfloat16_as_ushort(xl) | ((unsigned)__bfloat16_as_ushort(yl) << 16);
}
__device__ __forceinline__ unsigned cvsm(const void* p) {
    return (unsigned)__cvta_generic_to_shared(p);
}
__device__ __forceinline__ void ldsm4(unsigned* r, unsigned a) {
    asm volatile("ldmatrix.sync.aligned.m8n8.x4.shared.b16 {%0,%1,%2,%3}, [%4];"
                 : "=r"(r[0]), "=r"(r[1]), "=r"(r[2]), "=r"(r[3]) : "r"(a));
}
__device__ __forceinline__ void ldsm4t(unsigned* r, unsigned a) {
    asm volatile("ldmatrix.sync.aligned.m8n8.x4.trans.shared.b16 {%0,%1,%2,%3}, [%4];"
                 : "=r"(r[0]), "=r"(r[1]), "=r"(r[2]), "=r"(r[3]) : "r"(a));
}
__device__ __forceinline__ void ldsm2(unsigned& r0, unsigned& r1, unsigned a) {
    asm volatile("ldmatrix.sync.aligned.m8n8.x2.shared.b16 {%0,%1}, [%2];"
                 : "=r"(r0), "=r"(r1) : "r"(a));
}
__device__ __forceinline__ void ldsm2t(unsigned& r0, unsigned& r1, unsigned a) {
    asm volatile("ldmatrix.sync.aligned.m8n8.x2.trans.shared.b16 {%0,%1}, [%2];"
                 : "=r"(r0), "=r"(r1) : "r"(a));
}
__device__ __forceinline__ void mma_bf(float* c, const unsigned* a, unsigned b0, unsigned b1) {
    asm volatile(
        "mma.sync.aligned.m16n8k16.row.col.f32.bf16.bf16.f32 "
        "{%0,%1,%2,%3}, {%4,%5,%6,%7}, {%8,%9}, {%0,%1,%2,%3};\n"
        : "+f"(c[0]), "+f"(c[1]), "+f"(c[2]), "+f"(c[3])
        : "r"(a[0]), "r"(a[1]), "r"(a[2]), "r"(a[3]), "r"(b0), "r"(b1));
}
#define CPA16(dst, src) \
    asm volatile("cp.async.cg.shared.global [%0], [%1], 16;" :: "r"(dst), "l"(src))
#define CPA_COMMIT() asm volatile("cp.async.commit_group;")
#define CPA_WAIT1()  asm volatile("cp.async.wait_group 1;")
#define CPA_WAIT0()  asm volatile("cp.async.wait_group 0;")

__device__ __forceinline__ float fexpf(float x) {
    x = fmaxf(x, -87.0f);
    float t = fmaf(x, 1.4426950408889634f, 12582912.0f);
    int   ni = __float_as_int(t) - 0x4B400000;
    float n  = t - 12582912.0f;
    float f  = fmaf(x, 1.4426950408889634f, -n);
    float p = 1.333355626e-3f;
    p = fmaf(p, f, 9.618129633e-3f);
    p = fmaf(p, f, 5.550410866e-2f);
    p = fmaf(p, f, 2.402265069e-1f);
    p = fmaf(p, f, 6.931471806e-1f);
    p = fmaf(p, f, 1.0f);
    return p * __int_as_float((ni + 127) << 23);
}

// ---------------- conversion kernels ----------------
__global__ __launch_bounds__(256)
void cvt_plane(const float* __restrict__ src, int pid, int npairs) {
    int i = blockIdx.x * 256 + threadIdx.x;
    if (i >= npairs) return;
    ush *ph, *pl; pbuf(pid, ph, pl);
    float2 v = *(const float2*)(src + (size_t)2 * i);
    unsigned h, l; splitpack(v.x, v.y, h, l);
    *(unsigned*)&ph[(size_t)2 * i] = h;
    *(unsigned*)&pl[(size_t)2 * i] = l;
}

// Wq/Wk/Wv [H,D,64] -> combined planes [D, 3072], col = which*1024 + h*64 + c
__global__ __launch_bounds__(256)
void cvt_qkvw(const float* __restrict__ Wq, const float* __restrict__ Wk,
              const float* __restrict__ Wv) {
    int idx = blockIdx.x * 256 + threadIdx.x;     // over 1024*1536 pairs
    if (idx >= 1024 * 1536) return;
    const int d = idx / 1536, j3 = (idx % 1536) * 2;
    const int which = j3 >> 10, j = j3 & 1023, h = j >> 6, c = j & 63;
    const float* W = (which == 0) ? Wq : ((which == 1) ? Wk : Wv);
    const size_t s = (size_t)h * 65536 + (size_t)d * 64 + c;
    unsigned hh, ll; splitpack(W[s], W[s + 1], hh, ll);
    *(unsigned*)&g_wqh[(size_t)d * 3072 + j3] = hh;
    *(unsigned*)&g_wql[(size_t)d * 3072 + j3] = ll;
}

__global__ __launch_bounds__(256)
void cvt_bias(const float* __restrict__ bq, const float* __restrict__ bk,
              const float* __restrict__ bv) {
    int i = blockIdx.x * 256 + threadIdx.x;
    if (i >= 3072) return;
    const int which = i >> 10, j = i & 1023;
    const float* s = (which == 0) ? bq : ((which == 1) ? bk : bv);
    g_bqkv[i] = s[j];
}

// ---------------------------------------------------------------------------
// Pure-bf16-plane GEMM, 3-term split, cp.async 2-stage pipeline.
// BM=128 BN=128 BK=32, 256 threads, 8 warps (4x2), warp tile 32x64.
// smem halfs per stage: Ah[128*40] Al | Bh[32*136] Bl  (18944 halfs/stage)
// outMode: 0 fp32 (outId 0=g_attn, 1=g_y); 1 qkv scatter; 2 planes pbuf(outId)
// ---------------------------------------------------------------------------
#define GSTG 18944
#define GEMM_SMEM (2 * GSTG * 2)

__device__ __forceinline__ void gemm_issue(unsigned smB, int tid,
    const ush* __restrict__ Ah, const ush* __restrict__ Al,
    const ush* __restrict__ Bh, const ush* __restrict__ Bl,
    int brow, int bcol, int kk, int K, int N) {
#pragma unroll
    for (int j = 0; j < 8; j++) {
        const int id = j * 256 + tid;
        if (id < 1024) {
            const ush* sp = (id < 512) ? Ah : Al;
            const int c = id & 511, row = c >> 2, ch = c & 3;
            const ush* s = sp + (size_t)(brow + row) * K + kk + ch * 8;
            const unsigned dst = smB + (unsigned)(((id < 512 ? 0 : 5120) + row * 40 + ch * 8) * 2);
            CPA16(dst, s);
        } else {
            const ush* sp = (id < 1536) ? Bh : Bl;
            const int c = id & 511, row = c >> 4, ch = c & 15;
            const ush* s = sp + (size_t)(kk + row) * N + bcol + ch * 8;
            const unsigned dst = smB + (unsigned)((10240 + (id < 1536 ? 0 : 4352) + row * 136 + ch * 8) * 2);
            CPA16(dst, s);
        }
    }
}

__global__ __launch_bounds__(256, 2)
void gemm_bf(int aPid, int bPid, const float* __restrict__ bias, int qkvBias,
             int outMode, int outId, int N, int K, int relu)
{
    extern __shared__ __align__(16) ush gsm[];
    const unsigned smB = cvsm(gsm);

    ush *Ah, *Al, *Bh, *Bl;
    pbuf(aPid, Ah, Al);
    pbuf(bPid, Bh, Bl);

    const int tid = threadIdx.x;
    const int brow = blockIdx.y * 128, bcol = blockIdx.x * 128;
    const int warp = tid >> 5, lane = tid & 31;
    const int wm = warp >> 1, wn = warp & 1;
    const int grp = lane >> 2, tig = lane & 3;
    const int lr = lane & 7, ls = lane >> 3;

    float acc[2][8][4];
#pragma unroll
    for (int mt = 0; mt < 2; mt++)
#pragma unroll
        for (int nt = 0; nt < 8; nt++)
#pragma unroll
            for (int i = 0; i < 4; i++) acc[mt][nt][i] = 0.f;

    const int ntl = K / 32;
    gemm_issue(smB, tid, Ah, Al, Bh, Bl, brow, bcol, 0, K, N);
    CPA_COMMIT();

    for (int t = 0; t < ntl; t++) {
        if (t > 0) __syncthreads();
        if (t + 1 < ntl) {
            gemm_issue(smB + (unsigned)(((t + 1) & 1) * GSTG * 2), tid,
                       Ah, Al, Bh, Bl, brow, bcol, (t + 1) * 32, K, N);
            CPA_COMMIT();
            CPA_WAIT1();
        } else {
            CPA_WAIT0();
        }
        __syncthreads();

        const unsigned sb = smB + (unsigned)((t & 1) * GSTG * 2);
#pragma unroll
        for (int kc = 0; kc < 2; kc++) {
            unsigned ah[2][4], al[2][4];
#pragma unroll
            for (int mt = 0; mt < 2; mt++) {
                const unsigned ao = sb + (unsigned)(((wm * 32 + mt * 16 + lr + (ls & 1) * 8) * 40
                                                    + kc * 16 + (ls & 2) * 4) * 2);
                ldsm4(ah[mt], ao);
                ldsm4(al[mt], ao + 5120 * 2);
            }
#pragma unroll
            for (int nt2 = 0; nt2 < 4; nt2++) {
                const int row = kc * 16 + (ls & 1) * 8 + lr;
                const int col = wn * 64 + nt2 * 16 + (ls >> 1) * 8;
                const unsigned bo = sb + (unsigned)((10240 + row * 136 + col) * 2);
                unsigned bh[4], bl[4];
                ldsm4t(bh, bo);
                ldsm4t(bl, bo + 4352 * 2);
#pragma unroll
                for (int hf = 0; hf < 2; hf++) {
                    const int nt = 2 * nt2 + hf;
#pragma unroll
                    for (int mt = 0; mt < 2; mt++) {
                        mma_bf(acc[mt][nt], ah[mt], bh[2 * hf], bh[2 * hf + 1]);
                        mma_bf(acc[mt][nt], ah[mt], bl[2 * hf], bl[2 * hf + 1]);
                        mma_bf(acc[mt][nt], al[mt], bh[2 * hf], bh[2 * hf + 1]);
                    }
                }
            }
        }
    }

    // epilogue
#pragma unroll
    for (int mt = 0; mt < 2; mt++) {
#pragma unroll
        for (int nt = 0; nt < 8; nt++) {
            const int row = brow + wm * 32 + mt * 16 + grp;
            const int col = bcol + wn * 64 + nt * 8 + 2 * tig;
            float b0 = 0.f, b1 = 0.f;
            if (qkvBias)   { b0 = g_bqkv[col]; b1 = g_bqkv[col + 1]; }
            else if (bias) { b0 = bias[col];   b1 = bias[col + 1]; }
            float v00 = acc[mt][nt][0] + b0, v01 = acc[mt][nt][1] + b1;
            float v10 = acc[mt][nt][2] + b0, v11 = acc[mt][nt][3] + b1;
            if (relu) {
                v00 = fmaxf(v00, 0.f); v01 = fmaxf(v01, 0.f);
                v10 = fmaxf(v10, 0.f); v11 = fmaxf(v11, 0.f);
            }
            if (outMode == 0) {
                float* C = (outId == 0) ? g_attn : g_y;
                *(float2*)(C + (size_t)row * N + col)       = make_float2(v00, v01);
                *(float2*)(C + (size_t)(row + 8) * N + col) = make_float2(v10, v11);
            } else if (outMode == 1) {
                const int which = col >> 10;
                if (which == 0) { v00 *= 0.125f; v01 *= 0.125f; v10 *= 0.125f; v11 *= 0.125f; }
                ush *ph, *pl; pbuf(which, ph, pl);
                const int hh = (col >> 6) & 15, cc = col & 63;
                const int bb = row >> 11, tt = row & 2047;
                const size_t off = ((size_t)(bb * H_ + hh) * T_ + tt) * 64 + cc;
                unsigned uh, ul;
                splitpack(v00, v01, uh, ul);
                *(unsigned*)&ph[off] = uh; *(unsigned*)&pl[off] = ul;
                splitpack(v10, v11, uh, ul);
                *(unsigned*)&ph[off + 8 * 64] = uh; *(unsigned*)&pl[off + 8 * 64] = ul;
            } else {
                ush *ph, *pl; pbuf(outId, ph, pl);
                const size_t off = (size_t)row * N + col;
                unsigned uh, ul;
                splitpack(v00, v01, uh, ul);
                *(unsigned*)&ph[off] = uh; *(unsigned*)&pl[off] = ul;
                splitpack(v10, v11, uh, ul);
                *(unsigned*)&ph[off + (size_t)8 * N] = uh;
                *(unsigned*)&pl[off + (size_t)8 * N] = ul;
            }
        }
    }
}

// ---------------------------------------------------------------------------
// Tensor-core causal flash attention (as round 6, epilogue -> ocat planes)
// ---------------------------------------------------------------------------
#define ATTN_SMEM ((18432 + 4 * 4608) * 2)
__global__ __launch_bounds__(256)
void attn_tc() {
    extern __shared__ __align__(16) ush sh[];
    ush* QH = sh;
    ush* QL = sh + 9216;
    ush* KH = sh + 18432;

    const int qb = blockIdx.x, h = blockIdx.y, b = blockIdx.z;
    const int tid = threadIdx.x, warp = tid >> 5, lane = tid & 31;
    const int grp = lane >> 2, tig = lane & 3, lr = lane & 7;
    const int ls = lane >> 3, phs = ls & 1;
    const size_t pbase = (size_t)(b * H_ + h) * T_ * 64;
    const int rowbase = qb * 128 + warp * 16;
    const unsigned qhB = cvsm(QH), qlB = cvsm(QL), kvB = cvsm(KH);

#pragma unroll
    for (int j = 0; j < 8; j++) {
        const int id = j * 256 + tid;
        const int pl = id >> 10, wi = id & 1023;
        const int r = wi >> 3, c8 = (wi & 7) * 8;
        const ush* src = (pl ? g_ql : g_qh) + pbase + (size_t)(qb * 128 + r) * 64 + c8;
        *(uint4*)((pl ? QL : QH) + r * 72 + c8) = *(const uint4*)src;
    }

    float oacc[8][4];
#pragma unroll
    for (int nt = 0; nt < 8; nt++)
#pragma unroll
        for (int i = 0; i < 4; i++) oacc[nt][i] = 0.f;
    float m0 = -1e30f, m1 = -1e30f, l0 = 0.f, l1 = 0.f;

    const int ntiles = 2 * qb + 2;
    for (int jt = 0; jt < ntiles; jt++) {
        __syncthreads();
#pragma unroll
        for (int j = 0; j < 8; j++) {
            const int id = j * 256 + tid;
            const int pl = id >> 9, wi = id & 511;
            const int r = wi >> 3, c8 = (wi & 7) * 8;
            const ush* src;
            switch (pl) {
                case 0:  src = g_kh; break;
                case 1:  src = g_kl; break;
                case 2:  src = g_vh; break;
                default: src = g_vl; break;
            }
            src += pbase + (size_t)(jt * 64 + r) * 64 + c8;
            *(uint4*)(KH + pl * 4608 + r * 72 + c8) = *(const uint4*)src;
        }
        __syncthreads();
        if (jt * 64 > rowbase + 15) continue;

        float sacc[8][4];
#pragma unroll
        for (int nt = 0; nt < 8; nt++)
#pragma unroll
            for (int i = 0; i < 4; i++) sacc[nt][i] = 0.f;
#pragma unroll
        for (int kc = 0; kc < 4; kc++) {
            const unsigned aoff =
                (unsigned)(((warp * 16 + lr + (ls & 1) * 8) * 72 + kc * 16 + (ls & 2) * 4) * 2);
            unsigned qh[4], ql[4];
            ldsm4(qh, qhB + aoff);
            ldsm4(ql, qlB + aoff);
#pragma unroll
            for (int nt = 0; nt < 8; nt++) {
                const unsigned ko = kvB +
                    (unsigned)(((nt * 8 + lr) * 72 + kc * 16 + phs * 8) * 2);
                unsigned kh0, kh1, kl0, kl1;
                ldsm2(kh0, kh1, ko);
                ldsm2(kl0, kl1, ko + 4608 * 2);
                mma_bf(sacc[nt], qh, kh0, kh1);
                mma_bf(sacc[nt], qh, kl0, kl1);
                mma_bf(sacc[nt], ql, kh0, kh1);
            }
        }

        const int r0 = rowbase + grp, r1 = r0 + 8;
        if (jt * 64 + 63 > rowbase) {
#pragma unroll
            for (int nt = 0; nt < 8; nt++) {
                const int c0 = jt * 64 + nt * 8 + 2 * tig;
                if (c0     > r0) sacc[nt][0] = -1e30f;
                if (c0 + 1 > r0) sacc[nt][1] = -1e30f;
                if (c0     > r1) sacc[nt][2] = -1e30f;
                if (c0 + 1 > r1) sacc[nt][3] = -1e30f;
            }
        }
        float rm0 = -1e30f, rm1 = -1e30f;
#pragma unroll
        for (int nt = 0; nt < 8; nt++) {
            rm0 = fmaxf(rm0, fmaxf(sacc[nt][0], sacc[nt][1]));
            rm1 = fmaxf(rm1, fmaxf(sacc[nt][2], sacc[nt][3]));
        }
        rm0 = fmaxf(rm0, __shfl_xor_sync(0xffffffffu, rm0, 1));
        rm0 = fmaxf(rm0, __shfl_xor_sync(0xffffffffu, rm0, 2));
        rm1 = fmaxf(rm1, __shfl_xor_sync(0xffffffffu, rm1, 1));
        rm1 = fmaxf(rm1, __shfl_xor_sync(0xffffffffu, rm1, 2));
        const float mn0 = fmaxf(m0, rm0), mn1 = fmaxf(m1, rm1);
        const float al0 = fexpf(m0 - mn0), al1 = fexpf(m1 - mn1);
        float s0 = 0.f, s1 = 0.f;
#pragma unroll
        for (int nt = 0; nt < 8; nt++) {
            sacc[nt][0] = fexpf(sacc[nt][0] - mn0); s0 += sacc[nt][0];
            sacc[nt][1] = fexpf(sacc[nt][1] - mn0); s0 += sacc[nt][1];
            sacc[nt][2] = fexpf(sacc[nt][2] - mn1); s1 += sacc[nt][2];
            sacc[nt][3] = fexpf(sacc[nt][3] - mn1); s1 += sacc[nt][3];
        }
        s0 += __shfl_xor_sync(0xffffffffu, s0, 1);
        s0 += __shfl_xor_sync(0xffffffffu, s0, 2);
        s1 += __shfl_xor_sync(0xffffffffu, s1, 1);
        s1 += __shfl_xor_sync(0xffffffffu, s1, 2);
        l0 = l0 * al0 + s0; m0 = mn0;
        l1 = l1 * al1 + s1; m1 = mn1;
#pragma unroll
        for (int nt = 0; nt < 8; nt++) {
            oacc[nt][0] *= al0; oacc[nt][1] *= al0;
            oacc[nt][2] *= al1; oacc[nt][3] *= al1;
        }

#pragma unroll
        for (int kc = 0; kc < 4; kc++) {
            unsigned Ph[4], Pl[4];
            splitpack(sacc[2 * kc][0],     sacc[2 * kc][1],     Ph[0], Pl[0]);
            splitpack(sacc[2 * kc][2],     sacc[2 * kc][3],     Ph[1], Pl[1]);
            splitpack(sacc[2 * kc + 1][0], sacc[2 * kc + 1][1], Ph[2], Pl[2]);
            splitpack(sacc[2 * kc + 1][2], sacc[2 * kc + 1][3], Ph[3], Pl[3]);
#pragma unroll
            for (int nt = 0; nt < 8; nt++) {
                const unsigned vo = kvB +
                    (unsigned)((2 * 4608 + (kc * 16 + lr + phs * 8) * 72 + nt * 8) * 2);
                unsigned vh0, vh1, vl0, vl1;
                ldsm2t(vh0, vh1, vo);
                ldsm2t(vl0, vl1, vo + 4608 * 2);
                mma_bf(oacc[nt], Ph, vh0, vh1);
                mma_bf(oacc[nt], Ph, vl0, vl1);
                mma_bf(oacc[nt], Pl, vh0, vh1);
            }
        }
    }

    const float i0 = 1.f / l0, i1 = 1.f / l1;
    const int t0 = rowbase + grp;
#pragma unroll
    for (int nt = 0; nt < 8; nt++) {
        const int col = h * 64 + nt * 8 + 2 * tig;
        const size_t off = ((size_t)b * T_ + t0) * D_ + col;
        unsigned uh, ul;
        splitpack(oacc[nt][0] * i0, oacc[nt][1] * i0, uh, ul);
        *(unsigned*)&g_och[off] = uh; *(unsigned*)&g_ocl[off] = ul;
        splitpack(oacc[nt][2] * i1, oacc[nt][3] * i1, uh, ul);
        *(unsigned*)&g_och[off + (size_t)8 * D_] = uh;
        *(unsigned*)&g_ocl[off + (size_t)8 * D_] = ul;
    }
}

// ---------------- LayerNorm ----------------
__device__ __forceinline__ float block_sum(float v, float* red) {
    __syncthreads();
#pragma unroll
    for (int o = 16; o > 0; o >>= 1) v += __shfl_down_sync(0xffffffffu, v, o);
    if ((threadIdx.x & 31) == 0) red[threadIdx.x >> 5] = v;
    __syncthreads();
    if (threadIdx.x < 32) {
        float w = (threadIdx.x < 8) ? red[threadIdx.x] : 0.f;
#pragma unroll
        for (int o = 4; o > 0; o >>= 1) w += __shfl_down_sync(0xffffffffu, w, o);
        if (threadIdx.x == 0) red[0] = w;
    }
    __syncthreads();
    return red[0];
}

// aId: 0 = g_attn, 1 = g_y. Output: planes pbuf(outPid) if outPid>=0 else fp32 out_ext.
__global__ __launch_bounds__(256)
void ln_kernel(int aId, const float* __restrict__ res,
               const float* __restrict__ cbias, const float* __restrict__ g,
               const float* __restrict__ beta,
               float* __restrict__ out_ext, int outPid, int addPre) {
    __shared__ float pre[D_];
    __shared__ float red[32];
    const int row = blockIdx.x, tid = threadIdx.x;
    const float* ap = ((aId == 0) ? g_attn : g_y) + (size_t)row * D_;
    const float* rp = res ? res + (size_t)row * D_ : nullptr;

    float ls = 0.f;
    for (int i = tid * 2; i < D_; i += 512) {
        float2 a2 = *(const float2*)(ap + i);
        float v0 = a2.x, v1 = a2.y;
        if (rp)    { float2 r2 = *(const float2*)(rp + i);    v0 += r2.x; v1 += r2.y; }
        if (cbias) { float2 c2 = *(const float2*)(cbias + i); v0 += c2.x; v1 += c2.y; }
        pre[i] = v0; pre[i + 1] = v1;
        ls += v0 + v1;
    }
    const float mean = block_sum(ls, red) * (1.f / D_);
    float lv = 0.f;
    for (int i = tid * 2; i < D_; i += 512) {
        const float d0 = pre[i] - mean, d1 = pre[i + 1] - mean;
        lv += d0 * d0 + d1 * d1;
    }
    const float var = block_sum(lv, red) * (1.f / D_);
    const float rstd = rsqrtf(var + 1e-5f);
    for (int i = tid * 2; i < D_; i += 512) {
        const float p0 = pre[i], p1 = pre[i + 1];
        float z0 = (p0 - mean) * rstd * g[i]     + beta[i]     + (addPre ? p0 : 0.f);
        float z1 = (p1 - mean) * rstd * g[i + 1] + beta[i + 1] + (addPre ? p1 : 0.f);
        if (outPid >= 0) {
            ush *ph, *pl; pbuf(outPid, ph, pl);
            unsigned uh, ul; splitpack(z0, z1, uh, ul);
            *(unsigned*)&ph[(size_t)row * D_ + i] = uh;
            *(unsigned*)&pl[(size_t)row * D_ + i] = ul;
        } else {
            *(float2*)(out_ext + (size_t)row * D_ + i) = make_float2(z0, z1);
        }
    }
}

// ---------------- launcher ----------------
extern "C" void kernel_launch(void* const* d_in, const int* in_sizes, int n_in,
                              void* d_out, int out_size) {
    const float* x    = (const float*)d_in[0];
    const float* Wq   = (const float*)d_in[1];
    const float* bq   = (const float*)d_in[2];
    const float* Wk   = (const float*)d_in[3];
    const float* bk   = (const float*)d_in[4];
    const float* Wv   = (const float*)d_in[5];
    const float* bv   = (const float*)d_in[6];
    const float* Wo   = (const float*)d_in[7];
    const float* bo   = (const float*)d_in[8];
    const float* ln1g = (const float*)d_in[9];
    const float* ln1b = (const float*)d_in[10];
    const float* W1   = (const float*)d_in[11];
    const float* b1   = (const float*)d_in[12];
    const float* W2   = (const float*)d_in[13];
    const float* b2   = (const float*)d_in[14];
    const float* ln2g = (const float*)d_in[15];
    const float* ln2b = (const float*)d_in[16];
    float* out = (float*)d_out;

    // conversions (once per call; cheap)
    cvt_bias<<<12, 256>>>(bq, bk, bv);
    cvt_qkvw<<<6144, 256>>>(Wq, Wk, Wv);
    cvt_plane<<<8192, 256>>>(x,  6, MBT * D_ / 2);
    cvt_plane<<<2048, 256>>>(Wo, 8, D_ * D_ / 2);
    cvt_plane<<<8192, 256>>>(W1, 9, D_ * NF_ / 2);
    cvt_plane<<<8192, 256>>>(W2, 10, NF_ * D_ / 2);

    cudaFuncSetAttribute(gemm_bf, cudaFuncAttributeMaxDynamicSharedMemorySize, GEMM_SMEM);
    cudaFuncSetAttribute(attn_tc, cudaFuncAttributeMaxDynamicSharedMemorySize, ATTN_SMEM);

    // QKV fused: [4096,1024] @ [1024,3072] -> q/k/v planes (q pre-scaled)
    gemm_bf<<<dim3(3072 / 128, MBT / 128), 256, GEMM_SMEM>>>(6, 7, nullptr, 1, 1, 0, 3072, D_, 0);

    attn_tc<<<dim3(T_ / 128, H_, B_), 256, ATTN_SMEM>>>();

    // O-proj -> fp32 g_attn
    gemm_bf<<<dim3(D_ / 128, MBT / 128), 256, GEMM_SMEM>>>(3, 8, nullptr, 0, 0, 0, D_, D_, 0);

    // LN1 -> h planes
    ln_kernel<<<MBT, 256>>>(0, x, bo, ln1g, ln1b, nullptr, 4, 0);

    // FFN1 -> f planes (relu)
    gemm_bf<<<dim3(NF_ / 128, MBT / 128), 256, GEMM_SMEM>>>(4, 9, b1, 0, 2, 5, NF_, D_, 1);

    // FFN2 -> fp32 g_y
    gemm_bf<<<dim3(D_ / 128, MBT / 128), 256, GEMM_SMEM>>>(5, 10, b2, 0, 0, 1, D_, NF_, 0);

    // LN2 -> out (+y)
    ln_kernel<<<MBT, 256>>>(1, nullptr, nullptr, ln2g, ln2b, out, -1, 1);
}